// round 1
// baseline (speedup 1.0000x reference)
#include <cuda_runtime.h>
#include <math.h>

// Problem dims (fixed)
#define NB 8
#define NT 4096
#define ND 768
#define NH 12
#define NK 64
#define NM (NB*NT)          // 32768 rows

// ---------------------------------------------------------------------------
// Scratch (static device allocations are the sanctioned scratch mechanism)
// Buffer roles over the pipeline:
//   b0: xr -> k      b1: xk -> v      b2: xv -> y(normed)      b3: r
// ---------------------------------------------------------------------------
__device__ float g_buf0[(size_t)NM * ND];
__device__ float g_buf1[(size_t)NM * ND];
__device__ float g_buf2[(size_t)NM * ND];
__device__ float g_buf3[(size_t)NM * ND];
__device__ float g_mean[NB * NH];
__device__ float g_rstd[NB * NH];

// ---------------------------------------------------------------------------
// 1) Token-shift mixing: xr/xk/xv = x*mix + x_prev*(1-mix)
//    vectorized float4 (D % 4 == 0, each float4 stays within a row)
// ---------------------------------------------------------------------------
__global__ void mix_kernel(const float* __restrict__ x,
                           const float* __restrict__ tmr,
                           const float* __restrict__ tmk,
                           const float* __restrict__ tmv)
{
    size_t idx = (size_t)blockIdx.x * blockDim.x + threadIdx.x;
    const size_t n4 = (size_t)NM * ND / 4;
    if (idx >= n4) return;
    size_t e = idx * 4;
    int d = (int)(e % ND);
    int t = (int)((e / ND) % NT);

    float4 xc = reinterpret_cast<const float4*>(x)[idx];
    float4 xp = make_float4(0.f, 0.f, 0.f, 0.f);
    if (t != 0) xp = reinterpret_cast<const float4*>(x)[idx - ND / 4];

    float4 mr = reinterpret_cast<const float4*>(tmr)[d >> 2];
    float4 mk = reinterpret_cast<const float4*>(tmk)[d >> 2];
    float4 mv = reinterpret_cast<const float4*>(tmv)[d >> 2];

    float4 orv, okv, ovv;
    orv.x = xp.x + (xc.x - xp.x) * mr.x;  orv.y = xp.y + (xc.y - xp.y) * mr.y;
    orv.z = xp.z + (xc.z - xp.z) * mr.z;  orv.w = xp.w + (xc.w - xp.w) * mr.w;
    okv.x = xp.x + (xc.x - xp.x) * mk.x;  okv.y = xp.y + (xc.y - xp.y) * mk.y;
    okv.z = xp.z + (xc.z - xp.z) * mk.z;  okv.w = xp.w + (xc.w - xp.w) * mk.w;
    ovv.x = xp.x + (xc.x - xp.x) * mv.x;  ovv.y = xp.y + (xc.y - xp.y) * mv.y;
    ovv.z = xp.z + (xc.z - xp.z) * mv.z;  ovv.w = xp.w + (xc.w - xp.w) * mv.w;

    reinterpret_cast<float4*>(g_buf0)[idx] = orv;
    reinterpret_cast<float4*>(g_buf1)[idx] = okv;
    reinterpret_cast<float4*>(g_buf2)[idx] = ovv;
}

// ---------------------------------------------------------------------------
// 2) SGEMM: C[m,n] = sum_k A[m,k] * W[n,k]   (both operands K-contiguous)
//    M=32768, N=768, K=768. 128x128x16 tiles, 256 threads, 8x8 microtile.
//    ACT==1 applies sigmoid epilogue.
// ---------------------------------------------------------------------------
template <int ACT>
__global__ void __launch_bounds__(256)
gemm_kernel(const float* __restrict__ A,
            const float* __restrict__ W,
            float* __restrict__ C)
{
    constexpr int BM = 128, BN = 128, BK = 16;
    __shared__ float As[BK * BM];   // As[k][m]
    __shared__ float Bs[BK * BN];   // Bs[k][n]

    const int tid = threadIdx.x;
    const int m0 = blockIdx.y * BM;
    const int n0 = blockIdx.x * BN;
    const int tx = tid & 15;        // column group
    const int ty = tid >> 4;        // row group

    const int row_a = tid >> 2;             // 0..63
    const int kc4   = (tid & 3) * 4;        // 0,4,8,12

    float acc[8][8];
#pragma unroll
    for (int i = 0; i < 8; i++)
#pragma unroll
        for (int j = 0; j < 8; j++) acc[i][j] = 0.f;

    for (int kt = 0; kt < ND; kt += BK) {
#pragma unroll
        for (int i = 0; i < 2; i++) {
            int row = row_a + i * 64;
            float4 va = *reinterpret_cast<const float4*>(
                A + (size_t)(m0 + row) * ND + kt + kc4);
            As[(kc4 + 0) * BM + row] = va.x;
            As[(kc4 + 1) * BM + row] = va.y;
            As[(kc4 + 2) * BM + row] = va.z;
            As[(kc4 + 3) * BM + row] = va.w;
            float4 vb = *reinterpret_cast<const float4*>(
                W + (size_t)(n0 + row) * ND + kt + kc4);
            Bs[(kc4 + 0) * BN + row] = vb.x;
            Bs[(kc4 + 1) * BN + row] = vb.y;
            Bs[(kc4 + 2) * BN + row] = vb.z;
            Bs[(kc4 + 3) * BN + row] = vb.w;
        }
        __syncthreads();

#pragma unroll
        for (int kk = 0; kk < BK; kk++) {
            float a[8], b[8];
            *reinterpret_cast<float4*>(&a[0]) =
                *reinterpret_cast<const float4*>(&As[kk * BM + ty * 8]);
            *reinterpret_cast<float4*>(&a[4]) =
                *reinterpret_cast<const float4*>(&As[kk * BM + ty * 8 + 4]);
            *reinterpret_cast<float4*>(&b[0]) =
                *reinterpret_cast<const float4*>(&Bs[kk * BN + tx * 8]);
            *reinterpret_cast<float4*>(&b[4]) =
                *reinterpret_cast<const float4*>(&Bs[kk * BN + tx * 8 + 4]);
#pragma unroll
            for (int i = 0; i < 8; i++)
#pragma unroll
                for (int j = 0; j < 8; j++)
                    acc[i][j] = fmaf(a[i], b[j], acc[i][j]);
        }
        __syncthreads();
    }

#pragma unroll
    for (int i = 0; i < 8; i++) {
#pragma unroll
        for (int j = 0; j < 8; j++) {
            float v = acc[i][j];
            if (ACT == 1) v = 1.f / (1.f + __expf(-v));
            acc[i][j] = v;
        }
        float4* cp = reinterpret_cast<float4*>(
            C + (size_t)(m0 + ty * 8 + i) * ND + n0 + tx * 8);
        cp[0] = *reinterpret_cast<float4*>(&acc[i][0]);
        cp[1] = *reinterpret_cast<float4*>(&acc[i][4]);
    }
}

// ---------------------------------------------------------------------------
// 3) WKV recurrence + y = r*wkv + GroupNorm statistics.
//    1 block per (b,h), 64 threads (one per K-channel). The serial chain is
//    just num/den FMAs; exp/div/store are off the critical path.
// ---------------------------------------------------------------------------
__global__ void __launch_bounds__(64)
wkv_kernel(const float* __restrict__ kArr,   // g_buf0
           const float* __restrict__ vArr,   // g_buf1
           const float* __restrict__ rArr,   // g_buf3
           const float* __restrict__ td,
           const float* __restrict__ tf,
           float* __restrict__ y)            // g_buf2
{
    const int bh = blockIdx.x;          // b*NH + h
    const int b = bh / NH;
    const int h = bh - b * NH;
    const int kk = threadIdx.x;
    const int c = h * NK + kk;

    const float w  = expf(-expf(td[c]));
    const float eu = expf(tf[c]);
    const size_t base = (size_t)b * NT * ND + c;

    float num = 0.f, den = 0.f, s1 = 0.f, s2 = 0.f;

#pragma unroll 4
    for (int t = 0; t < NT; t++) {
        size_t idx = base + (size_t)t * ND;
        float kt = kArr[idx];
        float vt = vArr[idx];
        float rt = rArr[idx];
        float ek  = __expf(kt);
        float ekv = ek * vt;
        float numer = fmaf(eu, ekv, num);
        float denom = fmaf(eu, ek, den) + 1e-9f;
        float wkv = numer / denom;
        float yy = rt * wkv;
        y[idx] = yy;
        s1 += yy;
        s2 = fmaf(yy, yy, s2);
        num = fmaf(num, w, ekv);
        den = fmaf(den, w, ek);
    }

    // reduce sum / sumsq across 64 threads
#pragma unroll
    for (int off = 16; off > 0; off >>= 1) {
        s1 += __shfl_down_sync(0xffffffffu, s1, off);
        s2 += __shfl_down_sync(0xffffffffu, s2, off);
    }
    __shared__ float sh1[2], sh2[2];
    int wid = kk >> 5;
    if ((kk & 31) == 0) { sh1[wid] = s1; sh2[wid] = s2; }
    __syncthreads();
    if (kk == 0) {
        float S1 = sh1[0] + sh1[1];
        float S2 = sh2[0] + sh2[1];
        const float inv = 1.f / (float)(NT * NK);
        float mean = S1 * inv;
        float var  = S2 * inv - mean * mean;
        g_mean[bh] = mean;
        g_rstd[bh] = rsqrtf(var + 1e-5f);
    }
}

// ---------------------------------------------------------------------------
// 4) GroupNorm apply (in-place on g_buf2)
// ---------------------------------------------------------------------------
__global__ void norm_kernel(const float* __restrict__ gnw,
                            const float* __restrict__ gnb)
{
    size_t idx = (size_t)blockIdx.x * blockDim.x + threadIdx.x;
    const size_t n4 = (size_t)NM * ND / 4;
    if (idx >= n4) return;
    size_t e = idx * 4;
    int d = (int)(e % ND);
    int b = (int)(e / ((size_t)NT * ND));
    int h = d >> 6;                     // NK == 64
    float mean = g_mean[b * NH + h];
    float rstd = g_rstd[b * NH + h];

    float4 yv = reinterpret_cast<float4*>(g_buf2)[idx];
    float4 wv = reinterpret_cast<const float4*>(gnw)[d >> 2];
    float4 bv = reinterpret_cast<const float4*>(gnb)[d >> 2];
    yv.x = (yv.x - mean) * rstd * wv.x + bv.x;
    yv.y = (yv.y - mean) * rstd * wv.y + bv.y;
    yv.z = (yv.z - mean) * rstd * wv.z + bv.z;
    yv.w = (yv.w - mean) * rstd * wv.w + bv.w;
    reinterpret_cast<float4*>(g_buf2)[idx] = yv;
}

// ---------------------------------------------------------------------------
// host launcher (graph-capturable: kernel launches only)
// ---------------------------------------------------------------------------
extern "C" void kernel_launch(void* const* d_in, const int* in_sizes, int n_in,
                              void* d_out, int out_size)
{
    const float* x   = (const float*)d_in[0];
    const float* tmr = (const float*)d_in[1];
    const float* tmk = (const float*)d_in[2];
    const float* tmv = (const float*)d_in[3];
    const float* td  = (const float*)d_in[4];
    const float* tf  = (const float*)d_in[5];
    const float* Wr  = (const float*)d_in[6];
    const float* Wk  = (const float*)d_in[7];
    const float* Wv  = (const float*)d_in[8];
    const float* Wo  = (const float*)d_in[9];
    const float* gnw = (const float*)d_in[10];
    const float* gnb = (const float*)d_in[11];
    float* out = (float*)d_out;

    float *b0, *b1, *b2, *b3;
    cudaGetSymbolAddress((void**)&b0, g_buf0);
    cudaGetSymbolAddress((void**)&b1, g_buf1);
    cudaGetSymbolAddress((void**)&b2, g_buf2);
    cudaGetSymbolAddress((void**)&b3, g_buf3);

    const size_t n4 = (size_t)NM * ND / 4;
    const int blk = 256;
    const int grd = (int)((n4 + blk - 1) / blk);

    // 1) token shift mix: x -> b0=xr, b1=xk, b2=xv
    mix_kernel<<<grd, blk>>>(x, tmr, tmk, tmv);

    dim3 ggrid(ND / 128, NM / 128);   // (6, 256)
    // 2) projections
    gemm_kernel<1><<<ggrid, 256>>>(b0, Wr, b3);  // r = sigmoid(xr @ Wr^T)
    gemm_kernel<0><<<ggrid, 256>>>(b1, Wk, b0);  // k = xk @ Wk^T
    gemm_kernel<0><<<ggrid, 256>>>(b2, Wv, b1);  // v = xv @ Wv^T

    // 3) recurrence + GN stats: y -> b2
    wkv_kernel<<<NB * NH, 64>>>(b0, b1, b3, td, tf, b2);

    // 4) GroupNorm apply (in place)
    norm_kernel<<<grd, blk>>>(gnw, gnb);

    // 5) output projection
    gemm_kernel<0><<<ggrid, 256>>>(b2, Wo, out);
}

// round 2
// speedup vs baseline: 1.5548x; 1.5548x over previous
#include <cuda_runtime.h>
#include <math.h>

// Problem dims (fixed)
#define NB 8
#define NT 4096
#define ND 768
#define NH 12
#define NK 64
#define NM (NB*NT)          // 32768 rows
#define CC 64               // chunks along T
#define LL 64               // chunk length (CC*LL == NT)

// ---------------------------------------------------------------------------
// Scratch
//   b0: xr -> k      b1: xk -> v      b2: xv -> y(normed)      b3: r
// ---------------------------------------------------------------------------
__device__ float g_buf0[(size_t)NM * ND];
__device__ float g_buf1[(size_t)NM * ND];
__device__ float g_buf2[(size_t)NM * ND];
__device__ float g_buf3[(size_t)NM * ND];

// chunked-scan intermediates: [bh][chunk][k]
__device__ float g_Nloc[NB * NH * CC * NK];
__device__ float g_Dloc[NB * NH * CC * NK];
__device__ float g_InN [NB * NH * CC * NK];
__device__ float g_InD [NB * NH * CC * NK];
// GroupNorm partial sums per (b,h)
__device__ float g_s1[NB * NH];
__device__ float g_s2[NB * NH];

// ---------------------------------------------------------------------------
// 1) Token-shift mixing
// ---------------------------------------------------------------------------
__global__ void mix_kernel(const float* __restrict__ x,
                           const float* __restrict__ tmr,
                           const float* __restrict__ tmk,
                           const float* __restrict__ tmv)
{
    size_t idx = (size_t)blockIdx.x * blockDim.x + threadIdx.x;
    const size_t n4 = (size_t)NM * ND / 4;
    if (idx >= n4) return;
    size_t e = idx * 4;
    int d = (int)(e % ND);
    int t = (int)((e / ND) % NT);

    float4 xc = reinterpret_cast<const float4*>(x)[idx];
    float4 xp = make_float4(0.f, 0.f, 0.f, 0.f);
    if (t != 0) xp = reinterpret_cast<const float4*>(x)[idx - ND / 4];

    float4 mr = reinterpret_cast<const float4*>(tmr)[d >> 2];
    float4 mk = reinterpret_cast<const float4*>(tmk)[d >> 2];
    float4 mv = reinterpret_cast<const float4*>(tmv)[d >> 2];

    float4 orv, okv, ovv;
    orv.x = xp.x + (xc.x - xp.x) * mr.x;  orv.y = xp.y + (xc.y - xp.y) * mr.y;
    orv.z = xp.z + (xc.z - xp.z) * mr.z;  orv.w = xp.w + (xc.w - xp.w) * mr.w;
    okv.x = xp.x + (xc.x - xp.x) * mk.x;  okv.y = xp.y + (xc.y - xp.y) * mk.y;
    okv.z = xp.z + (xc.z - xp.z) * mk.z;  okv.w = xp.w + (xc.w - xp.w) * mk.w;
    ovv.x = xp.x + (xc.x - xp.x) * mv.x;  ovv.y = xp.y + (xc.y - xp.y) * mv.y;
    ovv.z = xp.z + (xc.z - xp.z) * mv.z;  ovv.w = xp.w + (xc.w - xp.w) * mv.w;

    reinterpret_cast<float4*>(g_buf0)[idx] = orv;
    reinterpret_cast<float4*>(g_buf1)[idx] = okv;
    reinterpret_cast<float4*>(g_buf2)[idx] = ovv;
}

// ---------------------------------------------------------------------------
// 2) SGEMM: C[m,n] = sum_k A[m,k] * W[n,k]
// ---------------------------------------------------------------------------
template <int ACT>
__global__ void __launch_bounds__(256)
gemm_kernel(const float* __restrict__ A,
            const float* __restrict__ W,
            float* __restrict__ C)
{
    constexpr int BM = 128, BN = 128, BK = 16;
    __shared__ float As[BK * BM];
    __shared__ float Bs[BK * BN];

    const int tid = threadIdx.x;
    const int m0 = blockIdx.y * BM;
    const int n0 = blockIdx.x * BN;
    const int tx = tid & 15;
    const int ty = tid >> 4;

    const int row_a = tid >> 2;
    const int kc4   = (tid & 3) * 4;

    float acc[8][8];
#pragma unroll
    for (int i = 0; i < 8; i++)
#pragma unroll
        for (int j = 0; j < 8; j++) acc[i][j] = 0.f;

    for (int kt = 0; kt < ND; kt += BK) {
#pragma unroll
        for (int i = 0; i < 2; i++) {
            int row = row_a + i * 64;
            float4 va = *reinterpret_cast<const float4*>(
                A + (size_t)(m0 + row) * ND + kt + kc4);
            As[(kc4 + 0) * BM + row] = va.x;
            As[(kc4 + 1) * BM + row] = va.y;
            As[(kc4 + 2) * BM + row] = va.z;
            As[(kc4 + 3) * BM + row] = va.w;
            float4 vb = *reinterpret_cast<const float4*>(
                W + (size_t)(n0 + row) * ND + kt + kc4);
            Bs[(kc4 + 0) * BN + row] = vb.x;
            Bs[(kc4 + 1) * BN + row] = vb.y;
            Bs[(kc4 + 2) * BN + row] = vb.z;
            Bs[(kc4 + 3) * BN + row] = vb.w;
        }
        __syncthreads();

#pragma unroll
        for (int kk = 0; kk < BK; kk++) {
            float a[8], b[8];
            *reinterpret_cast<float4*>(&a[0]) =
                *reinterpret_cast<const float4*>(&As[kk * BM + ty * 8]);
            *reinterpret_cast<float4*>(&a[4]) =
                *reinterpret_cast<const float4*>(&As[kk * BM + ty * 8 + 4]);
            *reinterpret_cast<float4*>(&b[0]) =
                *reinterpret_cast<const float4*>(&Bs[kk * BN + tx * 8]);
            *reinterpret_cast<float4*>(&b[4]) =
                *reinterpret_cast<const float4*>(&Bs[kk * BN + tx * 8 + 4]);
#pragma unroll
            for (int i = 0; i < 8; i++)
#pragma unroll
                for (int j = 0; j < 8; j++)
                    acc[i][j] = fmaf(a[i], b[j], acc[i][j]);
        }
        __syncthreads();
    }

#pragma unroll
    for (int i = 0; i < 8; i++) {
#pragma unroll
        for (int j = 0; j < 8; j++) {
            float v = acc[i][j];
            if (ACT == 1) v = 1.f / (1.f + __expf(-v));
            acc[i][j] = v;
        }
        float4* cp = reinterpret_cast<float4*>(
            C + (size_t)(m0 + ty * 8 + i) * ND + n0 + tx * 8);
        cp[0] = *reinterpret_cast<float4*>(&acc[i][0]);
        cp[1] = *reinterpret_cast<float4*>(&acc[i][4]);
    }
}

// ---------------------------------------------------------------------------
// 3a) WKV chunk aggregates: per (b,h,chunk), local decayed sums from 0 state.
//     Nloc = sum_i w^{L-1-i} ek_i v_i ;  Dloc = sum_i w^{L-1-i} ek_i
// ---------------------------------------------------------------------------
__global__ void __launch_bounds__(64)
wkv_chunk_agg(const float* __restrict__ kArr,
              const float* __restrict__ vArr,
              const float* __restrict__ td)
{
    const int bh = blockIdx.x;
    const int c  = blockIdx.y;
    const int b = bh / NH;
    const int h = bh - b * NH;
    const int kk = threadIdx.x;
    const int ch = h * NK + kk;

    const float w = __expf(-__expf(td[ch]));
    size_t base = (size_t)b * NT * ND + (size_t)c * LL * ND + ch;

    float N = 0.f, D = 0.f;
#pragma unroll 4
    for (int i = 0; i < LL; i++) {
        size_t idx = base + (size_t)i * ND;
        float ek = __expf(kArr[idx]);
        float vt = vArr[idx];
        N = fmaf(N, w, ek * vt);
        D = fmaf(D, w, ek);
    }
    int o = (bh * CC + c) * NK + kk;
    g_Nloc[o] = N;
    g_Dloc[o] = D;
}

// ---------------------------------------------------------------------------
// 3b) Scan across chunks per (b,h,k): carry_c = w^L * carry_{c-1} + Nloc_c
//     Stores the INCOMING state for each chunk. Also zeros GN stats.
// ---------------------------------------------------------------------------
__global__ void __launch_bounds__(64)
wkv_chunk_scan(const float* __restrict__ td)
{
    const int bh = blockIdx.x;
    const int b = bh / NH;
    const int h = bh - b * NH;
    const int kk = threadIdx.x;
    const int ch = h * NK + kk;

    if (kk == 0) { g_s1[bh] = 0.f; g_s2[bh] = 0.f; }

    const float wL = __expf(-(float)LL * __expf(td[ch]));

    float cN = 0.f, cD = 0.f;
    for (int c = 0; c < CC; c++) {
        int o = (bh * CC + c) * NK + kk;
        g_InN[o] = cN;
        g_InD[o] = cD;
        cN = fmaf(cN, wL, g_Nloc[o]);
        cD = fmaf(cD, wL, g_Dloc[o]);
    }
}

// ---------------------------------------------------------------------------
// 3c) WKV outputs per chunk from incoming state, + GN partial sums.
// ---------------------------------------------------------------------------
__global__ void __launch_bounds__(64)
wkv_out(const float* __restrict__ kArr,
        const float* __restrict__ vArr,
        const float* __restrict__ rArr,
        const float* __restrict__ td,
        const float* __restrict__ tf,
        float* __restrict__ y)
{
    const int bh = blockIdx.x;
    const int c  = blockIdx.y;
    const int b = bh / NH;
    const int h = bh - b * NH;
    const int kk = threadIdx.x;
    const int ch = h * NK + kk;

    const float w  = __expf(-__expf(td[ch]));
    const float eu = __expf(tf[ch]);
    size_t base = (size_t)b * NT * ND + (size_t)c * LL * ND + ch;

    int o = (bh * CC + c) * NK + kk;
    float num = g_InN[o];
    float den = g_InD[o];

    float s1 = 0.f, s2 = 0.f;
#pragma unroll 4
    for (int i = 0; i < LL; i++) {
        size_t idx = base + (size_t)i * ND;
        float kt = kArr[idx];
        float vt = vArr[idx];
        float rt = rArr[idx];
        float ek  = __expf(kt);
        float ekv = ek * vt;
        float numer = fmaf(eu, ekv, num);
        float denom = fmaf(eu, ek, den) + 1e-9f;
        float yy = rt * (numer / denom);
        y[idx] = yy;
        s1 += yy;
        s2 = fmaf(yy, yy, s2);
        num = fmaf(num, w, ekv);
        den = fmaf(den, w, ek);
    }

    // reduce GN sums over the 64 threads, then atomicAdd per (b,h)
#pragma unroll
    for (int off = 16; off > 0; off >>= 1) {
        s1 += __shfl_down_sync(0xffffffffu, s1, off);
        s2 += __shfl_down_sync(0xffffffffu, s2, off);
    }
    __shared__ float sh1[2], sh2[2];
    int wid = kk >> 5;
    if ((kk & 31) == 0) { sh1[wid] = s1; sh2[wid] = s2; }
    __syncthreads();
    if (kk == 0) {
        atomicAdd(&g_s1[bh], sh1[0] + sh1[1]);
        atomicAdd(&g_s2[bh], sh2[0] + sh2[1]);
    }
}

// ---------------------------------------------------------------------------
// 4) GroupNorm apply (in-place on g_buf2), stats finalized inline
// ---------------------------------------------------------------------------
__global__ void norm_kernel(const float* __restrict__ gnw,
                            const float* __restrict__ gnb)
{
    size_t idx = (size_t)blockIdx.x * blockDim.x + threadIdx.x;
    const size_t n4 = (size_t)NM * ND / 4;
    if (idx >= n4) return;
    size_t e = idx * 4;
    int d = (int)(e % ND);
    int b = (int)(e / ((size_t)NT * ND));
    int h = d >> 6;
    int bh = b * NH + h;

    const float inv = 1.f / (float)(NT * NK);
    float mean = g_s1[bh] * inv;
    float var  = g_s2[bh] * inv - mean * mean;
    float rstd = rsqrtf(var + 1e-5f);

    float4 yv = reinterpret_cast<float4*>(g_buf2)[idx];
    float4 wv = reinterpret_cast<const float4*>(gnw)[d >> 2];
    float4 bv = reinterpret_cast<const float4*>(gnb)[d >> 2];
    yv.x = (yv.x - mean) * rstd * wv.x + bv.x;
    yv.y = (yv.y - mean) * rstd * wv.y + bv.y;
    yv.z = (yv.z - mean) * rstd * wv.z + bv.z;
    yv.w = (yv.w - mean) * rstd * wv.w + bv.w;
    reinterpret_cast<float4*>(g_buf2)[idx] = yv;
}

// ---------------------------------------------------------------------------
// host launcher
// ---------------------------------------------------------------------------
extern "C" void kernel_launch(void* const* d_in, const int* in_sizes, int n_in,
                              void* d_out, int out_size)
{
    const float* x   = (const float*)d_in[0];
    const float* tmr = (const float*)d_in[1];
    const float* tmk = (const float*)d_in[2];
    const float* tmv = (const float*)d_in[3];
    const float* td  = (const float*)d_in[4];
    const float* tf  = (const float*)d_in[5];
    const float* Wr  = (const float*)d_in[6];
    const float* Wk  = (const float*)d_in[7];
    const float* Wv  = (const float*)d_in[8];
    const float* Wo  = (const float*)d_in[9];
    const float* gnw = (const float*)d_in[10];
    const float* gnb = (const float*)d_in[11];
    float* out = (float*)d_out;

    float *b0, *b1, *b2, *b3;
    cudaGetSymbolAddress((void**)&b0, g_buf0);
    cudaGetSymbolAddress((void**)&b1, g_buf1);
    cudaGetSymbolAddress((void**)&b2, g_buf2);
    cudaGetSymbolAddress((void**)&b3, g_buf3);

    const size_t n4 = (size_t)NM * ND / 4;
    const int blk = 256;
    const int grd = (int)((n4 + blk - 1) / blk);

    // 1) token shift mix: x -> b0=xr, b1=xk, b2=xv
    mix_kernel<<<grd, blk>>>(x, tmr, tmk, tmv);

    dim3 ggrid(ND / 128, NM / 128);
    // 2) projections
    gemm_kernel<1><<<ggrid, 256>>>(b0, Wr, b3);  // r = sigmoid(xr @ Wr^T)
    gemm_kernel<0><<<ggrid, 256>>>(b1, Wk, b0);  // k
    gemm_kernel<0><<<ggrid, 256>>>(b2, Wv, b1);  // v

    // 3) chunked parallel WKV scan: y -> b2
    dim3 wgrid(NB * NH, CC);
    wkv_chunk_agg <<<wgrid, 64>>>(b0, b1, td);
    wkv_chunk_scan<<<NB * NH, 64>>>(td);
    wkv_out       <<<wgrid, 64>>>(b0, b1, b3, td, tf, b2);

    // 4) GroupNorm apply (in place)
    norm_kernel<<<grd, blk>>>(gnw, gnb);

    // 5) output projection
    gemm_kernel<0><<<ggrid, 256>>>(b2, Wo, out);
}

// round 4
// speedup vs baseline: 3.4434x; 2.2147x over previous
#include <cuda_runtime.h>
#include <cuda_bf16.h>
#include <math.h>
#include <stdint.h>

// Problem dims (fixed)
#define NB 8
#define NT 4096
#define ND 768
#define NH 12
#define NK 64
#define NM (NB*NT)          // 32768 rows
#define CC 64               // chunks along T (wkv scan)
#define LL 64               // chunk length

// GEMM tiling
#define BM 128
#define BN 128
#define GBK 32
#define NCH (ND/GBK)        // 24 k-iterations
#define GRS 40              // smem row stride in bf16 elems (80B, conflict-free ldmatrix)
#define SUB (128*GRS)       // elems per subtile
#define STG (4*SUB)         // elems per stage (Ah,Al,Bh,Bl)
#define GEMM_SMEM_BYTES (2*STG*2)   // 81920 B

// ---------------------------------------------------------------------------
// Scratch buffers
// ---------------------------------------------------------------------------
__device__ float g_buf0[(size_t)NM * ND];   // k
__device__ float g_buf1[(size_t)NM * ND];   // v
__device__ float g_buf2[(size_t)NM * ND];   // y
__device__ float g_buf3[(size_t)NM * ND];   // r

__device__ __nv_bfloat16 g_xrh[(size_t)NM * ND];
__device__ __nv_bfloat16 g_xrl[(size_t)NM * ND];
__device__ __nv_bfloat16 g_xkh[(size_t)NM * ND];
__device__ __nv_bfloat16 g_xkl[(size_t)NM * ND];
__device__ __nv_bfloat16 g_xvh[(size_t)NM * ND];
__device__ __nv_bfloat16 g_xvl[(size_t)NM * ND];
__device__ __nv_bfloat16 g_Wh[4][ND * ND];
__device__ __nv_bfloat16 g_Wl[4][ND * ND];

// wkv chunked-scan intermediates
__device__ float g_Nloc[NB * NH * CC * NK];
__device__ float g_Dloc[NB * NH * CC * NK];
__device__ float g_InN [NB * NH * CC * NK];
__device__ float g_InD [NB * NH * CC * NK];
__device__ float g_s1[NB * NH];
__device__ float g_s2[NB * NH];

// ---------------------------------------------------------------------------
// helpers
// ---------------------------------------------------------------------------
__device__ __forceinline__ uint32_t smem_u32(const void* p) {
    uint32_t a;
    asm("{ .reg .u64 t; cvta.to.shared.u64 t, %1; cvt.u32.u64 %0, t; }"
        : "=r"(a) : "l"(p));
    return a;
}

__device__ __forceinline__ uint32_t packbf(float a, float b) {
    uint32_t r;
    asm("cvt.rn.bf16x2.f32 %0, %1, %2;" : "=r"(r) : "f"(b), "f"(a));
    return r;
}

__device__ __forceinline__ void split8(const float* m, uint4& hi, uint4& lo) {
    uint32_t h[4], l[4];
#pragma unroll
    for (int i = 0; i < 4; i++) {
        h[i] = packbf(m[2*i], m[2*i+1]);
        float f0 = __uint_as_float(h[i] << 16);
        float f1 = __uint_as_float(h[i] & 0xffff0000u);
        l[i] = packbf(m[2*i] - f0, m[2*i+1] - f1);
    }
    hi = make_uint4(h[0], h[1], h[2], h[3]);
    lo = make_uint4(l[0], l[1], l[2], l[3]);
}

__device__ __forceinline__ void ldsm4(uint32_t* r, uint32_t addr) {
    asm volatile("ldmatrix.sync.aligned.m8n8.x4.shared.b16 {%0,%1,%2,%3}, [%4];"
                 : "=r"(r[0]), "=r"(r[1]), "=r"(r[2]), "=r"(r[3]) : "r"(addr));
}

__device__ __forceinline__ void mma16816(float* c, const uint32_t* a, const uint32_t* b) {
    asm volatile(
        "mma.sync.aligned.m16n8k16.row.col.f32.bf16.bf16.f32 "
        "{%0,%1,%2,%3}, {%4,%5,%6,%7}, {%8,%9}, {%0,%1,%2,%3};"
        : "+f"(c[0]), "+f"(c[1]), "+f"(c[2]), "+f"(c[3])
        : "r"(a[0]), "r"(a[1]), "r"(a[2]), "r"(a[3]), "r"(b[0]), "r"(b[1]));
}

__device__ __forceinline__ void cpasync16(uint32_t saddr, const void* gptr) {
    asm volatile("cp.async.cg.shared.global [%0], [%1], 16;"
                 :: "r"(saddr), "l"(__cvta_generic_to_global(gptr)));
}

// ---------------------------------------------------------------------------
// 1) Token-shift mixing fused with bf16 hi/lo split
// ---------------------------------------------------------------------------
__global__ void mix_bf16(const float* __restrict__ x,
                         const float* __restrict__ tmr,
                         const float* __restrict__ tmk,
                         const float* __restrict__ tmv)
{
    size_t idx = (size_t)blockIdx.x * blockDim.x + threadIdx.x;
    const size_t n8 = (size_t)NM * ND / 8;
    if (idx >= n8) return;
    size_t e = idx * 8;
    int d = (int)(e % ND);
    int t = (int)((e / ND) % NT);

    const float4* x4 = (const float4*)x;
    float4 a0 = x4[idx*2], a1 = x4[idx*2+1];
    float4 p0 = make_float4(0.f,0.f,0.f,0.f), p1 = p0;
    if (t != 0) { p0 = x4[idx*2 - ND/4]; p1 = x4[idx*2 + 1 - ND/4]; }

    float xc[8] = {a0.x,a0.y,a0.z,a0.w,a1.x,a1.y,a1.z,a1.w};
    float xp[8] = {p0.x,p0.y,p0.z,p0.w,p1.x,p1.y,p1.z,p1.w};

    float mr[8], mk[8], mv[8];
    {
        float4 r0 = ((const float4*)tmr)[d>>2], r1 = ((const float4*)tmr)[(d>>2)+1];
        float4 k0 = ((const float4*)tmk)[d>>2], k1 = ((const float4*)tmk)[(d>>2)+1];
        float4 v0 = ((const float4*)tmv)[d>>2], v1 = ((const float4*)tmv)[(d>>2)+1];
        float mrr[8] = {r0.x,r0.y,r0.z,r0.w,r1.x,r1.y,r1.z,r1.w};
        float mkk[8] = {k0.x,k0.y,k0.z,k0.w,k1.x,k1.y,k1.z,k1.w};
        float mvv[8] = {v0.x,v0.y,v0.z,v0.w,v1.x,v1.y,v1.z,v1.w};
#pragma unroll
        for (int i = 0; i < 8; i++) {
            float dx = xc[i] - xp[i];
            mr[i] = fmaf(dx, mrr[i], xp[i]);
            mk[i] = fmaf(dx, mkk[i], xp[i]);
            mv[i] = fmaf(dx, mvv[i], xp[i]);
        }
    }
    uint4 hi, lo;
    split8(mr, hi, lo);
    ((uint4*)g_xrh)[idx] = hi; ((uint4*)g_xrl)[idx] = lo;
    split8(mk, hi, lo);
    ((uint4*)g_xkh)[idx] = hi; ((uint4*)g_xkl)[idx] = lo;
    split8(mv, hi, lo);
    ((uint4*)g_xvh)[idx] = hi; ((uint4*)g_xvl)[idx] = lo;
}

// ---------------------------------------------------------------------------
// fp32 -> bf16 hi/lo split (weights)
// ---------------------------------------------------------------------------
__global__ void split_kernel(const float* __restrict__ src,
                             __nv_bfloat16* __restrict__ h,
                             __nv_bfloat16* __restrict__ l, int n8)
{
    int idx = blockIdx.x * blockDim.x + threadIdx.x;
    if (idx >= n8) return;
    const float4* s4 = (const float4*)src;
    float4 a0 = s4[idx*2], a1 = s4[idx*2+1];
    float m[8] = {a0.x,a0.y,a0.z,a0.w,a1.x,a1.y,a1.z,a1.w};
    uint4 hi, lo;
    split8(m, hi, lo);
    ((uint4*)h)[idx] = hi;
    ((uint4*)l)[idx] = lo;
}

// ---------------------------------------------------------------------------
// 2) Tensor-core GEMM (mma.sync bf16, split 3-term):
//    C[m,n] = sum_k A[m,k]*W[n,k];  A=Ah+Al, W=Wh+Wl
// ---------------------------------------------------------------------------
template <int ACT>
__global__ void __launch_bounds__(256, 1)
gemm_mma(const __nv_bfloat16* __restrict__ Ah, const __nv_bfloat16* __restrict__ Al,
         const __nv_bfloat16* __restrict__ Bh, const __nv_bfloat16* __restrict__ Bl,
         float* __restrict__ C)
{
    extern __shared__ __nv_bfloat16 sm[];
    const uint32_t sb = smem_u32(sm);
    const int tid  = threadIdx.x;
    const int lane = tid & 31;
    const int wid  = tid >> 5;
    const int m0 = blockIdx.y * BM;
    const int n0 = blockIdx.x * BN;
    const int wm = (wid >> 2) * 64;     // warp M offset
    const int wn = (wid & 3) * 32;      // warp N offset

    float acc[4][4][4];
#pragma unroll
    for (int i = 0; i < 4; i++)
#pragma unroll
        for (int j = 0; j < 4; j++)
#pragma unroll
            for (int q = 0; q < 4; q++) acc[i][j][q] = 0.f;

    // ---- async stage loader ----
    auto do_issue = [&](int it, int stg) {
        const int kt = it * GBK;
        const uint32_t sbase = sb + (uint32_t)stg * (STG * 2);
#pragma unroll
        for (int j = 0; j < 2; j++) {
            int g   = tid + j * 256;     // 0..511
            int row = g >> 2;            // 0..127
            int kc  = (g & 3) * 8;       // 0,8,16,24
            uint32_t so = (uint32_t)(row * GRS + kc) * 2;
            size_t ga = (size_t)(m0 + row) * ND + kt + kc;
            size_t gb = (size_t)(n0 + row) * ND + kt + kc;
            cpasync16(sbase + so,             Ah + ga);
            cpasync16(sbase + SUB*2 + so,     Al + ga);
            cpasync16(sbase + 2*SUB*2 + so,   Bh + gb);
            cpasync16(sbase + 3*SUB*2 + so,   Bl + gb);
        }
        asm volatile("cp.async.commit_group;");
    };

    // ---- MMA on one stage ----
    auto do_compute = [&](int stg) {
        const uint32_t base = sb + (uint32_t)stg * (STG * 2);
        const int arow = wm + (lane & 15);
        const int acol0 = (lane >> 4) * 8;
        const int brow = wn + ((lane >> 4) << 3) + (lane & 7);
        const int bcol0 = ((lane >> 3) & 1) * 8;
#pragma unroll
        for (int ks = 0; ks < 2; ks++) {
            uint32_t ah[4][4], al[4][4], bh[4][2], bl[4][2];
            const int kofs = ks * 16;
#pragma unroll
            for (int mi = 0; mi < 4; mi++) {
                uint32_t ad = base + (uint32_t)((arow + mi * 16) * GRS + kofs + acol0) * 2;
                ldsm4(ah[mi], ad);
                ldsm4(al[mi], ad + SUB * 2);
            }
#pragma unroll
            for (int nj = 0; nj < 2; nj++) {
                uint32_t bd = base + 2*SUB*2
                            + (uint32_t)((brow + nj * 16) * GRS + kofs + bcol0) * 2;
                uint32_t t[4];
                ldsm4(t, bd);
                bh[nj*2][0] = t[0]; bh[nj*2][1] = t[1];
                bh[nj*2+1][0] = t[2]; bh[nj*2+1][1] = t[3];
                ldsm4(t, bd + SUB * 2);
                bl[nj*2][0] = t[0]; bl[nj*2][1] = t[1];
                bl[nj*2+1][0] = t[2]; bl[nj*2+1][1] = t[3];
            }
#pragma unroll
            for (int mi = 0; mi < 4; mi++)
#pragma unroll
                for (int ni = 0; ni < 4; ni++) {
                    mma16816(acc[mi][ni], ah[mi], bh[ni]);
                    mma16816(acc[mi][ni], ah[mi], bl[ni]);
                    mma16816(acc[mi][ni], al[mi], bh[ni]);
                }
        }
    };

    // ---- pipeline ----
    do_issue(0, 0);
    for (int it = 0; it < NCH; it++) {
        if (it + 1 < NCH) {
            do_issue(it + 1, (it + 1) & 1);
            asm volatile("cp.async.wait_group 1;");
        } else {
            asm volatile("cp.async.wait_group 0;");
        }
        __syncthreads();
        do_compute(it & 1);
        __syncthreads();
    }

    // ---- epilogue ----
#pragma unroll
    for (int mi = 0; mi < 4; mi++) {
        int row = m0 + wm + mi * 16 + (lane >> 2);
#pragma unroll
        for (int ni = 0; ni < 4; ni++) {
            int col = n0 + wn + ni * 8 + (lane & 3) * 2;
            float c0 = acc[mi][ni][0], c1 = acc[mi][ni][1];
            float c2 = acc[mi][ni][2], c3 = acc[mi][ni][3];
            if (ACT == 1) {
                c0 = 1.f / (1.f + __expf(-c0));
                c1 = 1.f / (1.f + __expf(-c1));
                c2 = 1.f / (1.f + __expf(-c2));
                c3 = 1.f / (1.f + __expf(-c3));
            }
            *(float2*)(C + (size_t)row * ND + col)       = make_float2(c0, c1);
            *(float2*)(C + (size_t)(row + 8) * ND + col) = make_float2(c2, c3);
        }
    }
}

// ---------------------------------------------------------------------------
// 3a) WKV chunk aggregates
// ---------------------------------------------------------------------------
__global__ void __launch_bounds__(64)
wkv_chunk_agg(const float* __restrict__ kArr,
              const float* __restrict__ vArr,
              const float* __restrict__ td)
{
    const int bh = blockIdx.x;
    const int c  = blockIdx.y;
    const int b = bh / NH;
    const int h = bh - b * NH;
    const int kk = threadIdx.x;
    const int ch = h * NK + kk;

    const float w = __expf(-__expf(td[ch]));
    size_t base = (size_t)b * NT * ND + (size_t)c * LL * ND + ch;

    float N = 0.f, D = 0.f;
#pragma unroll 4
    for (int i = 0; i < LL; i++) {
        size_t idx = base + (size_t)i * ND;
        float ek = __expf(kArr[idx]);
        float vt = vArr[idx];
        N = fmaf(N, w, ek * vt);
        D = fmaf(D, w, ek);
    }
    int o = (bh * CC + c) * NK + kk;
    g_Nloc[o] = N;
    g_Dloc[o] = D;
}

// ---------------------------------------------------------------------------
// 3b) scan across chunks
// ---------------------------------------------------------------------------
__global__ void __launch_bounds__(64)
wkv_chunk_scan(const float* __restrict__ td)
{
    const int bh = blockIdx.x;
    const int b = bh / NH;
    const int h = bh - b * NH;
    const int kk = threadIdx.x;
    const int ch = h * NK + kk;

    if (kk == 0) { g_s1[bh] = 0.f; g_s2[bh] = 0.f; }

    const float wL = __expf(-(float)LL * __expf(td[ch]));

    float cN = 0.f, cD = 0.f;
    for (int c = 0; c < CC; c++) {
        int o = (bh * CC + c) * NK + kk;
        g_InN[o] = cN;
        g_InD[o] = cD;
        cN = fmaf(cN, wL, g_Nloc[o]);
        cD = fmaf(cD, wL, g_Dloc[o]);
    }
}

// ---------------------------------------------------------------------------
// 3c) WKV outputs + GN partial sums
// ---------------------------------------------------------------------------
__global__ void __launch_bounds__(64)
wkv_out(const float* __restrict__ kArr,
        const float* __restrict__ vArr,
        const float* __restrict__ rArr,
        const float* __restrict__ td,
        const float* __restrict__ tf,
        float* __restrict__ y)
{
    const int bh = blockIdx.x;
    const int c  = blockIdx.y;
    const int b = bh / NH;
    const int h = bh - b * NH;
    const int kk = threadIdx.x;
    const int ch = h * NK + kk;

    const float w  = __expf(-__expf(td[ch]));
    const float eu = __expf(tf[ch]);
    size_t base = (size_t)b * NT * ND + (size_t)c * LL * ND + ch;

    int o = (bh * CC + c) * NK + kk;
    float num = g_InN[o];
    float den = g_InD[o];

    float s1 = 0.f, s2 = 0.f;
#pragma unroll 4
    for (int i = 0; i < LL; i++) {
        size_t idx = base + (size_t)i * ND;
        float kt = kArr[idx];
        float vt = vArr[idx];
        float rt = rArr[idx];
        float ek  = __expf(kt);
        float ekv = ek * vt;
        float numer = fmaf(eu, ekv, num);
        float denom = fmaf(eu, ek, den) + 1e-9f;
        float yy = rt * (numer / denom);
        y[idx] = yy;
        s1 += yy;
        s2 = fmaf(yy, yy, s2);
        num = fmaf(num, w, ekv);
        den = fmaf(den, w, ek);
    }

#pragma unroll
    for (int off = 16; off > 0; off >>= 1) {
        s1 += __shfl_down_sync(0xffffffffu, s1, off);
        s2 += __shfl_down_sync(0xffffffffu, s2, off);
    }
    __shared__ float sh1[2], sh2[2];
    int wd = kk >> 5;
    if ((kk & 31) == 0) { sh1[wd] = s1; sh2[wd] = s2; }
    __syncthreads();
    if (kk == 0) {
        atomicAdd(&g_s1[bh], sh1[0] + sh1[1]);
        atomicAdd(&g_s2[bh], sh2[0] + sh2[1]);
    }
}

// ---------------------------------------------------------------------------
// 4) GroupNorm apply fused with bf16 hi/lo split (y -> g_xrh/g_xrl)
// ---------------------------------------------------------------------------
__global__ void norm_bf16(const float* __restrict__ gnw,
                          const float* __restrict__ gnb)
{
    size_t idx = (size_t)blockIdx.x * blockDim.x + threadIdx.x;
    const size_t n8 = (size_t)NM * ND / 8;
    if (idx >= n8) return;
    size_t e = idx * 8;
    int d = (int)(e % ND);
    int b = (int)(e / ((size_t)NT * ND));
    int h = d >> 6;
    int bh = b * NH + h;

    const float inv = 1.f / (float)(NT * NK);
    float mean = g_s1[bh] * inv;
    float var  = g_s2[bh] * inv - mean * mean;
    float rstd = rsqrtf(var + 1e-5f);

    float4 y0 = ((const float4*)g_buf2)[idx*2];
    float4 y1 = ((const float4*)g_buf2)[idx*2 + 1];
    float4 w0 = ((const float4*)gnw)[d>>2], w1 = ((const float4*)gnw)[(d>>2)+1];
    float4 b0 = ((const float4*)gnb)[d>>2], b1 = ((const float4*)gnb)[(d>>2)+1];

    float yv[8] = {y0.x,y0.y,y0.z,y0.w,y1.x,y1.y,y1.z,y1.w};
    float wv[8] = {w0.x,w0.y,w0.z,w0.w,w1.x,w1.y,w1.z,w1.w};
    float bv[8] = {b0.x,b0.y,b0.z,b0.w,b1.x,b1.y,b1.z,b1.w};
    float m[8];
#pragma unroll
    for (int i = 0; i < 8; i++)
        m[i] = (yv[i] - mean) * rstd * wv[i] + bv[i];

    uint4 hi, lo;
    split8(m, hi, lo);
    ((uint4*)g_xrh)[idx] = hi;
    ((uint4*)g_xrl)[idx] = lo;
}

// ---------------------------------------------------------------------------
// host launcher
// ---------------------------------------------------------------------------
extern "C" void kernel_launch(void* const* d_in, const int* in_sizes, int n_in,
                              void* d_out, int out_size)
{
    const float* x   = (const float*)d_in[0];
    const float* tmr = (const float*)d_in[1];
    const float* tmk = (const float*)d_in[2];
    const float* tmv = (const float*)d_in[3];
    const float* td  = (const float*)d_in[4];
    const float* tf  = (const float*)d_in[5];
    const float* Wr  = (const float*)d_in[6];
    const float* Wk  = (const float*)d_in[7];
    const float* Wv  = (const float*)d_in[8];
    const float* Wo  = (const float*)d_in[9];
    const float* gnw = (const float*)d_in[10];
    const float* gnb = (const float*)d_in[11];
    float* out = (float*)d_out;

    float *b0, *b1, *b2, *b3;
    cudaGetSymbolAddress((void**)&b0, g_buf0);
    cudaGetSymbolAddress((void**)&b1, g_buf1);
    cudaGetSymbolAddress((void**)&b2, g_buf2);
    cudaGetSymbolAddress((void**)&b3, g_buf3);
    __nv_bfloat16 *xrh, *xrl, *xkh, *xkl, *xvh, *xvl, *wh, *wl;
    cudaGetSymbolAddress((void**)&xrh, g_xrh);
    cudaGetSymbolAddress((void**)&xrl, g_xrl);
    cudaGetSymbolAddress((void**)&xkh, g_xkh);
    cudaGetSymbolAddress((void**)&xkl, g_xkl);
    cudaGetSymbolAddress((void**)&xvh, g_xvh);
    cudaGetSymbolAddress((void**)&xvl, g_xvl);
    cudaGetSymbolAddress((void**)&wh, g_Wh);
    cudaGetSymbolAddress((void**)&wl, g_Wl);

    cudaFuncSetAttribute((const void*)gemm_mma<0>,
                         cudaFuncAttributeMaxDynamicSharedMemorySize, GEMM_SMEM_BYTES);
    cudaFuncSetAttribute((const void*)gemm_mma<1>,
                         cudaFuncAttributeMaxDynamicSharedMemorySize, GEMM_SMEM_BYTES);

    const size_t n8 = (size_t)NM * ND / 8;
    const int blk = 256;
    const int grd8 = (int)((n8 + blk - 1) / blk);
    const int wn8 = ND * ND / 8;
    const int wgrd = (wn8 + blk - 1) / blk;

    // 1) token-shift mix + bf16 split
    mix_bf16<<<grd8, blk>>>(x, tmr, tmk, tmv);
    // weight splits
    split_kernel<<<wgrd, blk>>>(Wr, wh + 0*(size_t)ND*ND, wl + 0*(size_t)ND*ND, wn8);
    split_kernel<<<wgrd, blk>>>(Wk, wh + 1*(size_t)ND*ND, wl + 1*(size_t)ND*ND, wn8);
    split_kernel<<<wgrd, blk>>>(Wv, wh + 2*(size_t)ND*ND, wl + 2*(size_t)ND*ND, wn8);
    split_kernel<<<wgrd, blk>>>(Wo, wh + 3*(size_t)ND*ND, wl + 3*(size_t)ND*ND, wn8);

    dim3 ggrid(ND / BN, NM / BM);   // (6, 256)
    // 2) projections on tensor cores (mma.sync)
    gemm_mma<1><<<ggrid, 256, GEMM_SMEM_BYTES>>>(xrh, xrl, wh + 0*(size_t)ND*ND, wl + 0*(size_t)ND*ND, b3);
    gemm_mma<0><<<ggrid, 256, GEMM_SMEM_BYTES>>>(xkh, xkl, wh + 1*(size_t)ND*ND, wl + 1*(size_t)ND*ND, b0);
    gemm_mma<0><<<ggrid, 256, GEMM_SMEM_BYTES>>>(xvh, xvl, wh + 2*(size_t)ND*ND, wl + 2*(size_t)ND*ND, b1);

    // 3) chunked parallel WKV scan: y -> b2
    dim3 wgrid(NB * NH, CC);
    wkv_chunk_agg <<<wgrid, 64>>>(b0, b1, td);
    wkv_chunk_scan<<<NB * NH, 64>>>(td);
    wkv_out       <<<wgrid, 64>>>(b0, b1, b3, td, tf, b2);

    // 4) GroupNorm apply + split (y -> xrh/xrl)
    norm_bf16<<<grd8, blk>>>(gnw, gnb);

    // 5) output projection
    gemm_mma<0><<<ggrid, 256, GEMM_SMEM_BYTES>>>(xrh, xrl, wh + 3*(size_t)ND*ND, wl + 3*(size_t)ND*ND, out);
}

// round 5
// speedup vs baseline: 3.9125x; 1.1363x over previous
#include <cuda_runtime.h>
#include <cuda_bf16.h>
#include <math.h>
#include <stdint.h>

// Problem dims (fixed)
#define NB 8
#define NT 4096
#define ND 768
#define NH 12
#define NK 64
#define NM (NB*NT)          // 32768 rows
#define CC 64               // chunks along T (wkv scan)
#define LL 64               // chunk length

// GEMM tiling
#define BM 128
#define BN 128
#define GBK 64
#define NCH (ND/GBK)        // 12 k-iterations
#define GRS 72              // smem row stride in bf16 elems (144B, conflict-free)
#define SUBB (128*GRS*2)    // bytes per subtile (18432)
#define STGB (4*SUBB)       // bytes per stage (73728)
#define GEMM_SMEM_BYTES (2*STGB)    // 147456

// ---------------------------------------------------------------------------
// Scratch buffers
// ---------------------------------------------------------------------------
__device__ float g_buf0[(size_t)NM * ND];   // k
__device__ float g_buf1[(size_t)NM * ND];   // v
__device__ float g_buf2[(size_t)NM * ND];   // y
__device__ float g_buf3[(size_t)NM * ND];   // r

__device__ __nv_bfloat16 g_xrh[(size_t)NM * ND];
__device__ __nv_bfloat16 g_xrl[(size_t)NM * ND];
__device__ __nv_bfloat16 g_xkh[(size_t)NM * ND];
__device__ __nv_bfloat16 g_xkl[(size_t)NM * ND];
__device__ __nv_bfloat16 g_xvh[(size_t)NM * ND];
__device__ __nv_bfloat16 g_xvl[(size_t)NM * ND];
__device__ __nv_bfloat16 g_Wh[4][ND * ND];
__device__ __nv_bfloat16 g_Wl[4][ND * ND];

// wkv chunked-scan intermediates
__device__ float g_Nloc[NB * NH * CC * NK];
__device__ float g_Dloc[NB * NH * CC * NK];
__device__ float g_InN [NB * NH * CC * NK];
__device__ float g_InD [NB * NH * CC * NK];
__device__ float g_s1[NB * NH];
__device__ float g_s2[NB * NH];

// ---------------------------------------------------------------------------
// helpers
// ---------------------------------------------------------------------------
__device__ __forceinline__ uint32_t smem_u32(const void* p) {
    uint32_t a;
    asm("{ .reg .u64 t; cvta.to.shared.u64 t, %1; cvt.u32.u64 %0, t; }"
        : "=r"(a) : "l"(p));
    return a;
}

__device__ __forceinline__ uint32_t packbf(float a, float b) {
    uint32_t r;
    asm("cvt.rn.bf16x2.f32 %0, %1, %2;" : "=r"(r) : "f"(b), "f"(a));
    return r;
}

__device__ __forceinline__ void split8(const float* m, uint4& hi, uint4& lo) {
    uint32_t h[4], l[4];
#pragma unroll
    for (int i = 0; i < 4; i++) {
        h[i] = packbf(m[2*i], m[2*i+1]);
        float f0 = __uint_as_float(h[i] << 16);
        float f1 = __uint_as_float(h[i] & 0xffff0000u);
        l[i] = packbf(m[2*i] - f0, m[2*i+1] - f1);
    }
    hi = make_uint4(h[0], h[1], h[2], h[3]);
    lo = make_uint4(l[0], l[1], l[2], l[3]);
}

__device__ __forceinline__ void ldsm4(uint32_t* r, uint32_t addr) {
    asm volatile("ldmatrix.sync.aligned.m8n8.x4.shared.b16 {%0,%1,%2,%3}, [%4];"
                 : "=r"(r[0]), "=r"(r[1]), "=r"(r[2]), "=r"(r[3]) : "r"(addr));
}

__device__ __forceinline__ void mma16816(float* c, const uint32_t* a, const uint32_t* b) {
    asm volatile(
        "mma.sync.aligned.m16n8k16.row.col.f32.bf16.bf16.f32 "
        "{%0,%1,%2,%3}, {%4,%5,%6,%7}, {%8,%9}, {%0,%1,%2,%3};"
        : "+f"(c[0]), "+f"(c[1]), "+f"(c[2]), "+f"(c[3])
        : "r"(a[0]), "r"(a[1]), "r"(a[2]), "r"(a[3]), "r"(b[0]), "r"(b[1]));
}

__device__ __forceinline__ void cpasync16(uint32_t saddr, const void* gptr) {
    asm volatile("cp.async.cg.shared.global [%0], [%1], 16;"
                 :: "r"(saddr), "l"(__cvta_generic_to_global(gptr)));
}

// ---------------------------------------------------------------------------
// 1) Token-shift mixing fused with bf16 hi/lo split
// ---------------------------------------------------------------------------
__global__ void mix_bf16(const float* __restrict__ x,
                         const float* __restrict__ tmr,
                         const float* __restrict__ tmk,
                         const float* __restrict__ tmv)
{
    size_t idx = (size_t)blockIdx.x * blockDim.x + threadIdx.x;
    const size_t n8 = (size_t)NM * ND / 8;
    if (idx >= n8) return;
    size_t e = idx * 8;
    int d = (int)(e % ND);
    int t = (int)((e / ND) % NT);

    const float4* x4 = (const float4*)x;
    float4 a0 = x4[idx*2], a1 = x4[idx*2+1];
    float4 p0 = make_float4(0.f,0.f,0.f,0.f), p1 = p0;
    if (t != 0) { p0 = x4[idx*2 - ND/4]; p1 = x4[idx*2 + 1 - ND/4]; }

    float xc[8] = {a0.x,a0.y,a0.z,a0.w,a1.x,a1.y,a1.z,a1.w};
    float xp[8] = {p0.x,p0.y,p0.z,p0.w,p1.x,p1.y,p1.z,p1.w};

    float mr[8], mk[8], mv[8];
    {
        float4 r0 = ((const float4*)tmr)[d>>2], r1 = ((const float4*)tmr)[(d>>2)+1];
        float4 k0 = ((const float4*)tmk)[d>>2], k1 = ((const float4*)tmk)[(d>>2)+1];
        float4 v0 = ((const float4*)tmv)[d>>2], v1 = ((const float4*)tmv)[(d>>2)+1];
        float mrr[8] = {r0.x,r0.y,r0.z,r0.w,r1.x,r1.y,r1.z,r1.w};
        float mkk[8] = {k0.x,k0.y,k0.z,k0.w,k1.x,k1.y,k1.z,k1.w};
        float mvv[8] = {v0.x,v0.y,v0.z,v0.w,v1.x,v1.y,v1.z,v1.w};
#pragma unroll
        for (int i = 0; i < 8; i++) {
            float dx = xc[i] - xp[i];
            mr[i] = fmaf(dx, mrr[i], xp[i]);
            mk[i] = fmaf(dx, mkk[i], xp[i]);
            mv[i] = fmaf(dx, mvv[i], xp[i]);
        }
    }
    uint4 hi, lo;
    split8(mr, hi, lo);
    ((uint4*)g_xrh)[idx] = hi; ((uint4*)g_xrl)[idx] = lo;
    split8(mk, hi, lo);
    ((uint4*)g_xkh)[idx] = hi; ((uint4*)g_xkl)[idx] = lo;
    split8(mv, hi, lo);
    ((uint4*)g_xvh)[idx] = hi; ((uint4*)g_xvl)[idx] = lo;
}

// ---------------------------------------------------------------------------
// fp32 -> bf16 hi/lo split (weights)
// ---------------------------------------------------------------------------
__global__ void split_kernel(const float* __restrict__ src,
                             __nv_bfloat16* __restrict__ h,
                             __nv_bfloat16* __restrict__ l, int n8)
{
    int idx = blockIdx.x * blockDim.x + threadIdx.x;
    if (idx >= n8) return;
    const float4* s4 = (const float4*)src;
    float4 a0 = s4[idx*2], a1 = s4[idx*2+1];
    float m[8] = {a0.x,a0.y,a0.z,a0.w,a1.x,a1.y,a1.z,a1.w};
    uint4 hi, lo;
    split8(m, hi, lo);
    ((uint4*)h)[idx] = hi;
    ((uint4*)l)[idx] = lo;
}

// ---------------------------------------------------------------------------
// 2) Batched tensor-core GEMM (mma.sync bf16, 3-term split):
//    For each z: C[z][m,n] = sum_k A[z][m,k]*W[z][n,k]
//    Single __syncthreads per k-iter, 2-stage cp.async pipeline, GBK=64.
// ---------------------------------------------------------------------------
struct GemmArgs {
    const __nv_bfloat16* Ah[3];
    const __nv_bfloat16* Al[3];
    const __nv_bfloat16* Bh[3];
    const __nv_bfloat16* Bl[3];
    float* C[3];
    int actmask;   // bit z: apply sigmoid
};

__global__ void __launch_bounds__(256, 1)
gemm_mma_batched(GemmArgs args)
{
    extern __shared__ __nv_bfloat16 smraw[];
    const uint32_t sb = smem_u32(smraw);
    const int tid  = threadIdx.x;
    const int lane = tid & 31;
    const int wid  = tid >> 5;
    const int z  = blockIdx.z;
    const int m0 = blockIdx.y * BM;
    const int n0 = blockIdx.x * BN;
    const int wm = (wid >> 2) * 64;
    const int wn = (wid & 3) * 32;

    const __nv_bfloat16* __restrict__ Ah = args.Ah[z];
    const __nv_bfloat16* __restrict__ Al = args.Al[z];
    const __nv_bfloat16* __restrict__ Bh = args.Bh[z];
    const __nv_bfloat16* __restrict__ Bl = args.Bl[z];
    float* __restrict__ C = args.C[z];
    const bool act = (args.actmask >> z) & 1;

    float acc[4][4][4];
#pragma unroll
    for (int i = 0; i < 4; i++)
#pragma unroll
        for (int j = 0; j < 4; j++)
#pragma unroll
            for (int q = 0; q < 4; q++) acc[i][j][q] = 0.f;

    // ---- stage loader: 64KB per stage, 16 cp.async x 16B per thread ----
    auto do_issue = [&](int it, int stg) {
        const int kt = it * GBK;
        const uint32_t sbase = sb + (uint32_t)stg * STGB;
#pragma unroll
        for (int j = 0; j < 4; j++) {
            int g   = tid + j * 256;     // 0..1023
            int row = g >> 3;            // 0..127
            int kc  = (g & 7) * 8;       // 0..56
            uint32_t so = (uint32_t)(row * GRS + kc) * 2;
            size_t ga = (size_t)(m0 + row) * ND + kt + kc;
            size_t gb = (size_t)(n0 + row) * ND + kt + kc;
            cpasync16(sbase + so,            Ah + ga);
            cpasync16(sbase + SUBB + so,     Al + ga);
            cpasync16(sbase + 2*SUBB + so,   Bh + gb);
            cpasync16(sbase + 3*SUBB + so,   Bl + gb);
        }
        asm volatile("cp.async.commit_group;");
    };

    // ---- compute one stage: 4 x k16 steps ----
    auto do_compute = [&](int stg) {
        const uint32_t base = sb + (uint32_t)stg * STGB;
        const int arow = wm + (lane & 15);
        const int acol0 = (lane >> 4) * 8;
        const int brow = wn + ((lane >> 4) << 3) + (lane & 7);
        const int bcol0 = ((lane >> 3) & 1) * 8;
#pragma unroll
        for (int ks = 0; ks < 4; ks++) {
            uint32_t ah[4][4], al[4][4], bh[4][2], bl[4][2];
            const int kofs = ks * 16;
#pragma unroll
            for (int mi = 0; mi < 4; mi++) {
                uint32_t ad = base + (uint32_t)((arow + mi * 16) * GRS + kofs + acol0) * 2;
                ldsm4(ah[mi], ad);
                ldsm4(al[mi], ad + SUBB);
            }
#pragma unroll
            for (int nj = 0; nj < 2; nj++) {
                uint32_t bd = base + 2*SUBB
                            + (uint32_t)((brow + nj * 16) * GRS + kofs + bcol0) * 2;
                uint32_t t[4];
                ldsm4(t, bd);
                bh[nj*2][0] = t[0]; bh[nj*2][1] = t[1];
                bh[nj*2+1][0] = t[2]; bh[nj*2+1][1] = t[3];
                ldsm4(t, bd + SUBB);
                bl[nj*2][0] = t[0]; bl[nj*2][1] = t[1];
                bl[nj*2+1][0] = t[2]; bl[nj*2+1][1] = t[3];
            }
#pragma unroll
            for (int mi = 0; mi < 4; mi++)
#pragma unroll
                for (int ni = 0; ni < 4; ni++) {
                    mma16816(acc[mi][ni], ah[mi], bh[ni]);
                    mma16816(acc[mi][ni], ah[mi], bl[ni]);
                    mma16816(acc[mi][ni], al[mi], bh[ni]);
                }
        }
    };

    // ---- pipeline: single sync per iteration ----
    do_issue(0, 0);
    for (int it = 0; it < NCH; it++) {
        asm volatile("cp.async.wait_group 0;");
        __syncthreads();   // stage `it` visible to all; compute(it-1) finished by all
        if (it + 1 < NCH) do_issue(it + 1, (it + 1) & 1);
        do_compute(it & 1);
    }

    // ---- epilogue ----
#pragma unroll
    for (int mi = 0; mi < 4; mi++) {
        int row = m0 + wm + mi * 16 + (lane >> 2);
#pragma unroll
        for (int ni = 0; ni < 4; ni++) {
            int col = n0 + wn + ni * 8 + (lane & 3) * 2;
            float c0 = acc[mi][ni][0], c1 = acc[mi][ni][1];
            float c2 = acc[mi][ni][2], c3 = acc[mi][ni][3];
            if (act) {
                c0 = 1.f / (1.f + __expf(-c0));
                c1 = 1.f / (1.f + __expf(-c1));
                c2 = 1.f / (1.f + __expf(-c2));
                c3 = 1.f / (1.f + __expf(-c3));
            }
            *(float2*)(C + (size_t)row * ND + col)       = make_float2(c0, c1);
            *(float2*)(C + (size_t)(row + 8) * ND + col) = make_float2(c2, c3);
        }
    }
}

// ---------------------------------------------------------------------------
// 3a) WKV chunk aggregates
// ---------------------------------------------------------------------------
__global__ void __launch_bounds__(64)
wkv_chunk_agg(const float* __restrict__ kArr,
              const float* __restrict__ vArr,
              const float* __restrict__ td)
{
    const int bh = blockIdx.x;
    const int c  = blockIdx.y;
    const int b = bh / NH;
    const int h = bh - b * NH;
    const int kk = threadIdx.x;
    const int ch = h * NK + kk;

    const float w = __expf(-__expf(td[ch]));
    size_t base = (size_t)b * NT * ND + (size_t)c * LL * ND + ch;

    float N = 0.f, D = 0.f;
#pragma unroll 4
    for (int i = 0; i < LL; i++) {
        size_t idx = base + (size_t)i * ND;
        float ek = __expf(kArr[idx]);
        float vt = vArr[idx];
        N = fmaf(N, w, ek * vt);
        D = fmaf(D, w, ek);
    }
    int o = (bh * CC + c) * NK + kk;
    g_Nloc[o] = N;
    g_Dloc[o] = D;
}

// ---------------------------------------------------------------------------
// 3b) scan across chunks
// ---------------------------------------------------------------------------
__global__ void __launch_bounds__(64)
wkv_chunk_scan(const float* __restrict__ td)
{
    const int bh = blockIdx.x;
    const int b = bh / NH;
    const int h = bh - b * NH;
    const int kk = threadIdx.x;
    const int ch = h * NK + kk;

    if (kk == 0) { g_s1[bh] = 0.f; g_s2[bh] = 0.f; }

    const float wL = __expf(-(float)LL * __expf(td[ch]));

    float cN = 0.f, cD = 0.f;
    for (int c = 0; c < CC; c++) {
        int o = (bh * CC + c) * NK + kk;
        g_InN[o] = cN;
        g_InD[o] = cD;
        cN = fmaf(cN, wL, g_Nloc[o]);
        cD = fmaf(cD, wL, g_Dloc[o]);
    }
}

// ---------------------------------------------------------------------------
// 3c) WKV outputs + GN partial sums
// ---------------------------------------------------------------------------
__global__ void __launch_bounds__(64)
wkv_out(const float* __restrict__ kArr,
        const float* __restrict__ vArr,
        const float* __restrict__ rArr,
        const float* __restrict__ td,
        const float* __restrict__ tf,
        float* __restrict__ y)
{
    const int bh = blockIdx.x;
    const int c  = blockIdx.y;
    const int b = bh / NH;
    const int h = bh - b * NH;
    const int kk = threadIdx.x;
    const int ch = h * NK + kk;

    const float w  = __expf(-__expf(td[ch]));
    const float eu = __expf(tf[ch]);
    size_t base = (size_t)b * NT * ND + (size_t)c * LL * ND + ch;

    int o = (bh * CC + c) * NK + kk;
    float num = g_InN[o];
    float den = g_InD[o];

    float s1 = 0.f, s2 = 0.f;
#pragma unroll 4
    for (int i = 0; i < LL; i++) {
        size_t idx = base + (size_t)i * ND;
        float kt = kArr[idx];
        float vt = vArr[idx];
        float rt = rArr[idx];
        float ek  = __expf(kt);
        float ekv = ek * vt;
        float numer = fmaf(eu, ekv, num);
        float denom = fmaf(eu, ek, den) + 1e-9f;
        float yy = rt * (numer / denom);
        y[idx] = yy;
        s1 += yy;
        s2 = fmaf(yy, yy, s2);
        num = fmaf(num, w, ekv);
        den = fmaf(den, w, ek);
    }

#pragma unroll
    for (int off = 16; off > 0; off >>= 1) {
        s1 += __shfl_down_sync(0xffffffffu, s1, off);
        s2 += __shfl_down_sync(0xffffffffu, s2, off);
    }
    __shared__ float sh1[2], sh2[2];
    int wd = kk >> 5;
    if ((kk & 31) == 0) { sh1[wd] = s1; sh2[wd] = s2; }
    __syncthreads();
    if (kk == 0) {
        atomicAdd(&g_s1[bh], sh1[0] + sh1[1]);
        atomicAdd(&g_s2[bh], sh2[0] + sh2[1]);
    }
}

// ---------------------------------------------------------------------------
// 4) GroupNorm apply fused with bf16 hi/lo split (y -> g_xrh/g_xrl)
// ---------------------------------------------------------------------------
__global__ void norm_bf16(const float* __restrict__ gnw,
                          const float* __restrict__ gnb)
{
    size_t idx = (size_t)blockIdx.x * blockDim.x + threadIdx.x;
    const size_t n8 = (size_t)NM * ND / 8;
    if (idx >= n8) return;
    size_t e = idx * 8;
    int d = (int)(e % ND);
    int b = (int)(e / ((size_t)NT * ND));
    int h = d >> 6;
    int bh = b * NH + h;

    const float inv = 1.f / (float)(NT * NK);
    float mean = g_s1[bh] * inv;
    float var  = g_s2[bh] * inv - mean * mean;
    float rstd = rsqrtf(var + 1e-5f);

    float4 y0 = ((const float4*)g_buf2)[idx*2];
    float4 y1 = ((const float4*)g_buf2)[idx*2 + 1];
    float4 w0 = ((const float4*)gnw)[d>>2], w1 = ((const float4*)gnw)[(d>>2)+1];
    float4 b0 = ((const float4*)gnb)[d>>2], b1 = ((const float4*)gnb)[(d>>2)+1];

    float yv[8] = {y0.x,y0.y,y0.z,y0.w,y1.x,y1.y,y1.z,y1.w};
    float wv[8] = {w0.x,w0.y,w0.z,w0.w,w1.x,w1.y,w1.z,w1.w};
    float bv[8] = {b0.x,b0.y,b0.z,b0.w,b1.x,b1.y,b1.z,b1.w};
    float m[8];
#pragma unroll
    for (int i = 0; i < 8; i++)
        m[i] = (yv[i] - mean) * rstd * wv[i] + bv[i];

    uint4 hi, lo;
    split8(m, hi, lo);
    ((uint4*)g_xrh)[idx] = hi;
    ((uint4*)g_xrl)[idx] = lo;
}

// ---------------------------------------------------------------------------
// host launcher
// ---------------------------------------------------------------------------
extern "C" void kernel_launch(void* const* d_in, const int* in_sizes, int n_in,
                              void* d_out, int out_size)
{
    const float* x   = (const float*)d_in[0];
    const float* tmr = (const float*)d_in[1];
    const float* tmk = (const float*)d_in[2];
    const float* tmv = (const float*)d_in[3];
    const float* td  = (const float*)d_in[4];
    const float* tf  = (const float*)d_in[5];
    const float* Wr  = (const float*)d_in[6];
    const float* Wk  = (const float*)d_in[7];
    const float* Wv  = (const float*)d_in[8];
    const float* Wo  = (const float*)d_in[9];
    const float* gnw = (const float*)d_in[10];
    const float* gnb = (const float*)d_in[11];
    float* out = (float*)d_out;

    float *b0, *b1, *b2, *b3;
    cudaGetSymbolAddress((void**)&b0, g_buf0);
    cudaGetSymbolAddress((void**)&b1, g_buf1);
    cudaGetSymbolAddress((void**)&b2, g_buf2);
    cudaGetSymbolAddress((void**)&b3, g_buf3);
    __nv_bfloat16 *xrh, *xrl, *xkh, *xkl, *xvh, *xvl, *wh, *wl;
    cudaGetSymbolAddress((void**)&xrh, g_xrh);
    cudaGetSymbolAddress((void**)&xrl, g_xrl);
    cudaGetSymbolAddress((void**)&xkh, g_xkh);
    cudaGetSymbolAddress((void**)&xkl, g_xkl);
    cudaGetSymbolAddress((void**)&xvh, g_xvh);
    cudaGetSymbolAddress((void**)&xvl, g_xvl);
    cudaGetSymbolAddress((void**)&wh, g_Wh);
    cudaGetSymbolAddress((void**)&wl, g_Wl);

    cudaFuncSetAttribute((const void*)gemm_mma_batched,
                         cudaFuncAttributeMaxDynamicSharedMemorySize, GEMM_SMEM_BYTES);

    const size_t n8 = (size_t)NM * ND / 8;
    const int blk = 256;
    const int grd8 = (int)((n8 + blk - 1) / blk);
    const int wn8 = ND * ND / 8;
    const int wgrd = (wn8 + blk - 1) / blk;

    // launches 0-3: weight splits (keeps big GEMM at launch index 5 for ncu)
    split_kernel<<<wgrd, blk>>>(Wr, wh + 0*(size_t)ND*ND, wl + 0*(size_t)ND*ND, wn8);
    split_kernel<<<wgrd, blk>>>(Wk, wh + 1*(size_t)ND*ND, wl + 1*(size_t)ND*ND, wn8);
    split_kernel<<<wgrd, blk>>>(Wv, wh + 2*(size_t)ND*ND, wl + 2*(size_t)ND*ND, wn8);
    split_kernel<<<wgrd, blk>>>(Wo, wh + 3*(size_t)ND*ND, wl + 3*(size_t)ND*ND, wn8);

    // launch 4: token-shift mix + bf16 split
    mix_bf16<<<grd8, blk>>>(x, tmr, tmk, tmv);

    // launch 5: fused r/k/v projections (batched over z)
    GemmArgs qkv;
    qkv.Ah[0] = xrh; qkv.Al[0] = xrl;
    qkv.Bh[0] = wh + 0*(size_t)ND*ND; qkv.Bl[0] = wl + 0*(size_t)ND*ND;
    qkv.C[0]  = b3;                 // r (sigmoid)
    qkv.Ah[1] = xkh; qkv.Al[1] = xkl;
    qkv.Bh[1] = wh + 1*(size_t)ND*ND; qkv.Bl[1] = wl + 1*(size_t)ND*ND;
    qkv.C[1]  = b0;                 // k
    qkv.Ah[2] = xvh; qkv.Al[2] = xvl;
    qkv.Bh[2] = wh + 2*(size_t)ND*ND; qkv.Bl[2] = wl + 2*(size_t)ND*ND;
    qkv.C[2]  = b1;                 // v
    qkv.actmask = 1;
    dim3 ggrid(ND / BN, NM / BM, 3);
    gemm_mma_batched<<<ggrid, 256, GEMM_SMEM_BYTES>>>(qkv);

    // chunked parallel WKV scan: y -> b2
    dim3 wgrid(NB * NH, CC);
    wkv_chunk_agg <<<wgrid, 64>>>(b0, b1, td);
    wkv_chunk_scan<<<NB * NH, 64>>>(td);
    wkv_out       <<<wgrid, 64>>>(b0, b1, b3, td, tf, b2);

    // GroupNorm apply + split (y -> xrh/xrl)
    norm_bf16<<<grd8, blk>>>(gnw, gnb);

    // output projection
    GemmArgs og;
    og.Ah[0] = xrh; og.Al[0] = xrl;
    og.Bh[0] = wh + 3*(size_t)ND*ND; og.Bl[0] = wl + 3*(size_t)ND*ND;
    og.C[0]  = out;
    og.Ah[1] = og.Ah[2] = xrh; og.Al[1] = og.Al[2] = xrl;
    og.Bh[1] = og.Bh[2] = og.Bh[0]; og.Bl[1] = og.Bl[2] = og.Bl[0];
    og.C[1] = og.C[2] = out;
    og.actmask = 0;
    dim3 ogrid(ND / BN, NM / BM, 1);
    gemm_mma_batched<<<ogrid, 256, GEMM_SMEM_BYTES>>>(og);
}

// round 6
// speedup vs baseline: 4.1123x; 1.0511x over previous
#include <cuda_runtime.h>
#include <cuda_bf16.h>
#include <math.h>
#include <stdint.h>

// Problem dims (fixed)
#define NB 8
#define NT 4096
#define ND 768
#define NH 12
#define NK 64
#define NM (NB*NT)          // 32768 rows
#define CC 64               // chunks along T (wkv scan)
#define LL 64               // chunk length

// GEMM tiling: 2 CTAs/SM (80KB smem total, <=128 regs)
#define BM 128
#define BN 128
#define GBK 32
#define NCH (ND/GBK)        // 24 k-iterations
#define GRS 40              // smem row stride in bf16 elems (80B, conflict-free ldmatrix)
#define SUBB (128*GRS*2)    // bytes per subtile (10240)
#define STGB (4*SUBB)       // bytes per stage (40960)
#define GEMM_SMEM_BYTES (2*STGB)    // 81920

// ---------------------------------------------------------------------------
// Scratch buffers
// ---------------------------------------------------------------------------
__device__ float g_buf0[(size_t)NM * ND];   // k
__device__ float g_buf1[(size_t)NM * ND];   // v
__device__ float g_buf2[(size_t)NM * ND];   // y
__device__ float g_buf3[(size_t)NM * ND];   // r

__device__ __nv_bfloat16 g_xrh[(size_t)NM * ND];
__device__ __nv_bfloat16 g_xrl[(size_t)NM * ND];
__device__ __nv_bfloat16 g_xkh[(size_t)NM * ND];
__device__ __nv_bfloat16 g_xkl[(size_t)NM * ND];
__device__ __nv_bfloat16 g_xvh[(size_t)NM * ND];
__device__ __nv_bfloat16 g_xvl[(size_t)NM * ND];
__device__ __nv_bfloat16 g_Wh[4][ND * ND];
__device__ __nv_bfloat16 g_Wl[4][ND * ND];

// wkv chunked-scan intermediates
__device__ float g_Nloc[NB * NH * CC * NK];
__device__ float g_Dloc[NB * NH * CC * NK];
__device__ float g_InN [NB * NH * CC * NK];
__device__ float g_InD [NB * NH * CC * NK];
__device__ float g_s1[NB * NH];
__device__ float g_s2[NB * NH];

// ---------------------------------------------------------------------------
// helpers
// ---------------------------------------------------------------------------
__device__ __forceinline__ uint32_t smem_u32(const void* p) {
    uint32_t a;
    asm("{ .reg .u64 t; cvta.to.shared.u64 t, %1; cvt.u32.u64 %0, t; }"
        : "=r"(a) : "l"(p));
    return a;
}

__device__ __forceinline__ uint32_t packbf(float a, float b) {
    uint32_t r;
    asm("cvt.rn.bf16x2.f32 %0, %1, %2;" : "=r"(r) : "f"(b), "f"(a));
    return r;
}

__device__ __forceinline__ void split8(const float* m, uint4& hi, uint4& lo) {
    uint32_t h[4], l[4];
#pragma unroll
    for (int i = 0; i < 4; i++) {
        h[i] = packbf(m[2*i], m[2*i+1]);
        float f0 = __uint_as_float(h[i] << 16);
        float f1 = __uint_as_float(h[i] & 0xffff0000u);
        l[i] = packbf(m[2*i] - f0, m[2*i+1] - f1);
    }
    hi = make_uint4(h[0], h[1], h[2], h[3]);
    lo = make_uint4(l[0], l[1], l[2], l[3]);
}

__device__ __forceinline__ void ldsm4(uint32_t* r, uint32_t addr) {
    asm volatile("ldmatrix.sync.aligned.m8n8.x4.shared.b16 {%0,%1,%2,%3}, [%4];"
                 : "=r"(r[0]), "=r"(r[1]), "=r"(r[2]), "=r"(r[3]) : "r"(addr));
}

__device__ __forceinline__ void mma16816(float* c, const uint32_t* a, const uint32_t* b) {
    asm volatile(
        "mma.sync.aligned.m16n8k16.row.col.f32.bf16.bf16.f32 "
        "{%0,%1,%2,%3}, {%4,%5,%6,%7}, {%8,%9}, {%0,%1,%2,%3};"
        : "+f"(c[0]), "+f"(c[1]), "+f"(c[2]), "+f"(c[3])
        : "r"(a[0]), "r"(a[1]), "r"(a[2]), "r"(a[3]), "r"(b[0]), "r"(b[1]));
}

__device__ __forceinline__ void cpasync16(uint32_t saddr, const void* gptr) {
    asm volatile("cp.async.cg.shared.global [%0], [%1], 16;"
                 :: "r"(saddr), "l"(__cvta_generic_to_global(gptr)));
}

// ---------------------------------------------------------------------------
// 1) Token-shift mixing fused with bf16 hi/lo split
// ---------------------------------------------------------------------------
__global__ void mix_bf16(const float* __restrict__ x,
                         const float* __restrict__ tmr,
                         const float* __restrict__ tmk,
                         const float* __restrict__ tmv)
{
    size_t idx = (size_t)blockIdx.x * blockDim.x + threadIdx.x;
    const size_t n8 = (size_t)NM * ND / 8;
    if (idx >= n8) return;
    size_t e = idx * 8;
    int d = (int)(e % ND);
    int t = (int)((e / ND) % NT);

    const float4* x4 = (const float4*)x;
    float4 a0 = x4[idx*2], a1 = x4[idx*2+1];
    float4 p0 = make_float4(0.f,0.f,0.f,0.f), p1 = p0;
    if (t != 0) { p0 = x4[idx*2 - ND/4]; p1 = x4[idx*2 + 1 - ND/4]; }

    float xc[8] = {a0.x,a0.y,a0.z,a0.w,a1.x,a1.y,a1.z,a1.w};
    float xp[8] = {p0.x,p0.y,p0.z,p0.w,p1.x,p1.y,p1.z,p1.w};

    float mr[8], mk[8], mv[8];
    {
        float4 r0 = ((const float4*)tmr)[d>>2], r1 = ((const float4*)tmr)[(d>>2)+1];
        float4 k0 = ((const float4*)tmk)[d>>2], k1 = ((const float4*)tmk)[(d>>2)+1];
        float4 v0 = ((const float4*)tmv)[d>>2], v1 = ((const float4*)tmv)[(d>>2)+1];
        float mrr[8] = {r0.x,r0.y,r0.z,r0.w,r1.x,r1.y,r1.z,r1.w};
        float mkk[8] = {k0.x,k0.y,k0.z,k0.w,k1.x,k1.y,k1.z,k1.w};
        float mvv[8] = {v0.x,v0.y,v0.z,v0.w,v1.x,v1.y,v1.z,v1.w};
#pragma unroll
        for (int i = 0; i < 8; i++) {
            float dx = xc[i] - xp[i];
            mr[i] = fmaf(dx, mrr[i], xp[i]);
            mk[i] = fmaf(dx, mkk[i], xp[i]);
            mv[i] = fmaf(dx, mvv[i], xp[i]);
        }
    }
    uint4 hi, lo;
    split8(mr, hi, lo);
    ((uint4*)g_xrh)[idx] = hi; ((uint4*)g_xrl)[idx] = lo;
    split8(mk, hi, lo);
    ((uint4*)g_xkh)[idx] = hi; ((uint4*)g_xkl)[idx] = lo;
    split8(mv, hi, lo);
    ((uint4*)g_xvh)[idx] = hi; ((uint4*)g_xvl)[idx] = lo;
}

// ---------------------------------------------------------------------------
// fp32 -> bf16 hi/lo split (weights)
// ---------------------------------------------------------------------------
__global__ void split_kernel(const float* __restrict__ src,
                             __nv_bfloat16* __restrict__ h,
                             __nv_bfloat16* __restrict__ l, int n8)
{
    int idx = blockIdx.x * blockDim.x + threadIdx.x;
    if (idx >= n8) return;
    const float4* s4 = (const float4*)src;
    float4 a0 = s4[idx*2], a1 = s4[idx*2+1];
    float m[8] = {a0.x,a0.y,a0.z,a0.w,a1.x,a1.y,a1.z,a1.w};
    uint4 hi, lo;
    split8(m, hi, lo);
    ((uint4*)h)[idx] = hi;
    ((uint4*)l)[idx] = lo;
}

// ---------------------------------------------------------------------------
// 2) Batched tensor-core GEMM (mma.sync bf16, 3-term split), 2 CTAs/SM
// ---------------------------------------------------------------------------
struct GemmArgs {
    const __nv_bfloat16* Ah[3];
    const __nv_bfloat16* Al[3];
    const __nv_bfloat16* Bh[3];
    const __nv_bfloat16* Bl[3];
    float* C[3];
    int actmask;   // bit z: apply sigmoid
};

__global__ void __launch_bounds__(256, 2)
gemm_mma_batched(GemmArgs args)
{
    extern __shared__ __nv_bfloat16 smraw[];
    const uint32_t sb = smem_u32(smraw);
    const int tid  = threadIdx.x;
    const int lane = tid & 31;
    const int wid  = tid >> 5;
    const int z  = blockIdx.z;
    const int m0 = blockIdx.y * BM;
    const int n0 = blockIdx.x * BN;
    const int wm = (wid >> 2) * 64;
    const int wn = (wid & 3) * 32;

    const __nv_bfloat16* __restrict__ Ah = args.Ah[z];
    const __nv_bfloat16* __restrict__ Al = args.Al[z];
    const __nv_bfloat16* __restrict__ Bh = args.Bh[z];
    const __nv_bfloat16* __restrict__ Bl = args.Bl[z];
    float* __restrict__ C = args.C[z];
    const bool act = (args.actmask >> z) & 1;

    float acc[4][4][4];
#pragma unroll
    for (int i = 0; i < 4; i++)
#pragma unroll
        for (int j = 0; j < 4; j++)
#pragma unroll
            for (int q = 0; q < 4; q++) acc[i][j][q] = 0.f;

    // ---- stage loader: 40KB per stage, 8 cp.async x 16B per thread ----
    auto do_issue = [&](int it, int stg) {
        const int kt = it * GBK;
        const uint32_t sbase = sb + (uint32_t)stg * STGB;
#pragma unroll
        for (int j = 0; j < 2; j++) {
            int g   = tid + j * 256;     // 0..511
            int row = g >> 2;            // 0..127
            int kc  = (g & 3) * 8;       // 0,8,16,24
            uint32_t so = (uint32_t)(row * GRS + kc) * 2;
            size_t ga = (size_t)(m0 + row) * ND + kt + kc;
            size_t gb = (size_t)(n0 + row) * ND + kt + kc;
            cpasync16(sbase + so,            Ah + ga);
            cpasync16(sbase + SUBB + so,     Al + ga);
            cpasync16(sbase + 2*SUBB + so,   Bh + gb);
            cpasync16(sbase + 3*SUBB + so,   Bl + gb);
        }
        asm volatile("cp.async.commit_group;");
    };

    // ---- compute one stage: 2 x k16 steps ----
    auto do_compute = [&](int stg) {
        const uint32_t base = sb + (uint32_t)stg * STGB;
        const int arow = wm + (lane & 15);
        const int acol0 = (lane >> 4) * 8;
        const int brow = wn + ((lane >> 4) << 3) + (lane & 7);
        const int bcol0 = ((lane >> 3) & 1) * 8;
#pragma unroll
        for (int ks = 0; ks < 2; ks++) {
            uint32_t ah[4][4], al[4][4], bh[4][2], bl[4][2];
            const int kofs = ks * 16;
#pragma unroll
            for (int mi = 0; mi < 4; mi++) {
                uint32_t ad = base + (uint32_t)((arow + mi * 16) * GRS + kofs + acol0) * 2;
                ldsm4(ah[mi], ad);
                ldsm4(al[mi], ad + SUBB);
            }
#pragma unroll
            for (int nj = 0; nj < 2; nj++) {
                uint32_t bd = base + 2*SUBB
                            + (uint32_t)((brow + nj * 16) * GRS + kofs + bcol0) * 2;
                uint32_t t[4];
                ldsm4(t, bd);
                bh[nj*2][0] = t[0]; bh[nj*2][1] = t[1];
                bh[nj*2+1][0] = t[2]; bh[nj*2+1][1] = t[3];
                ldsm4(t, bd + SUBB);
                bl[nj*2][0] = t[0]; bl[nj*2][1] = t[1];
                bl[nj*2+1][0] = t[2]; bl[nj*2+1][1] = t[3];
            }
#pragma unroll
            for (int mi = 0; mi < 4; mi++)
#pragma unroll
                for (int ni = 0; ni < 4; ni++) {
                    mma16816(acc[mi][ni], ah[mi], bh[ni]);
                    mma16816(acc[mi][ni], ah[mi], bl[ni]);
                    mma16816(acc[mi][ni], al[mi], bh[ni]);
                }
        }
    };

    // ---- pipeline: single sync per iteration ----
    do_issue(0, 0);
    for (int it = 0; it < NCH; it++) {
        asm volatile("cp.async.wait_group 0;");
        __syncthreads();   // stage `it` visible; compute(it-1) finished by all
        if (it + 1 < NCH) do_issue(it + 1, (it + 1) & 1);
        do_compute(it & 1);
    }

    // ---- epilogue ----
#pragma unroll
    for (int mi = 0; mi < 4; mi++) {
        int row = m0 + wm + mi * 16 + (lane >> 2);
#pragma unroll
        for (int ni = 0; ni < 4; ni++) {
            int col = n0 + wn + ni * 8 + (lane & 3) * 2;
            float c0 = acc[mi][ni][0], c1 = acc[mi][ni][1];
            float c2 = acc[mi][ni][2], c3 = acc[mi][ni][3];
            if (act) {
                c0 = 1.f / (1.f + __expf(-c0));
                c1 = 1.f / (1.f + __expf(-c1));
                c2 = 1.f / (1.f + __expf(-c2));
                c3 = 1.f / (1.f + __expf(-c3));
            }
            *(float2*)(C + (size_t)row * ND + col)       = make_float2(c0, c1);
            *(float2*)(C + (size_t)(row + 8) * ND + col) = make_float2(c2, c3);
        }
    }
}

// ---------------------------------------------------------------------------
// 3a) WKV chunk aggregates
// ---------------------------------------------------------------------------
__global__ void __launch_bounds__(64)
wkv_chunk_agg(const float* __restrict__ kArr,
              const float* __restrict__ vArr,
              const float* __restrict__ td)
{
    const int bh = blockIdx.x;
    const int c  = blockIdx.y;
    const int b = bh / NH;
    const int h = bh - b * NH;
    const int kk = threadIdx.x;
    const int ch = h * NK + kk;

    const float w = __expf(-__expf(td[ch]));
    size_t base = (size_t)b * NT * ND + (size_t)c * LL * ND + ch;

    float N = 0.f, D = 0.f;
#pragma unroll 4
    for (int i = 0; i < LL; i++) {
        size_t idx = base + (size_t)i * ND;
        float ek = __expf(kArr[idx]);
        float vt = vArr[idx];
        N = fmaf(N, w, ek * vt);
        D = fmaf(D, w, ek);
    }
    int o = (bh * CC + c) * NK + kk;
    g_Nloc[o] = N;
    g_Dloc[o] = D;
}

// ---------------------------------------------------------------------------
// 3b) scan across chunks
// ---------------------------------------------------------------------------
__global__ void __launch_bounds__(64)
wkv_chunk_scan(const float* __restrict__ td)
{
    const int bh = blockIdx.x;
    const int b = bh / NH;
    const int h = bh - b * NH;
    const int kk = threadIdx.x;
    const int ch = h * NK + kk;

    if (kk == 0) { g_s1[bh] = 0.f; g_s2[bh] = 0.f; }

    const float wL = __expf(-(float)LL * __expf(td[ch]));

    float cN = 0.f, cD = 0.f;
    for (int c = 0; c < CC; c++) {
        int o = (bh * CC + c) * NK + kk;
        g_InN[o] = cN;
        g_InD[o] = cD;
        cN = fmaf(cN, wL, g_Nloc[o]);
        cD = fmaf(cD, wL, g_Dloc[o]);
    }
}

// ---------------------------------------------------------------------------
// 3c) WKV outputs + GN partial sums
// ---------------------------------------------------------------------------
__global__ void __launch_bounds__(64)
wkv_out(const float* __restrict__ kArr,
        const float* __restrict__ vArr,
        const float* __restrict__ rArr,
        const float* __restrict__ td,
        const float* __restrict__ tf,
        float* __restrict__ y)
{
    const int bh = blockIdx.x;
    const int c  = blockIdx.y;
    const int b = bh / NH;
    const int h = bh - b * NH;
    const int kk = threadIdx.x;
    const int ch = h * NK + kk;

    const float w  = __expf(-__expf(td[ch]));
    const float eu = __expf(tf[ch]);
    size_t base = (size_t)b * NT * ND + (size_t)c * LL * ND + ch;

    int o = (bh * CC + c) * NK + kk;
    float num = g_InN[o];
    float den = g_InD[o];

    float s1 = 0.f, s2 = 0.f;
#pragma unroll 4
    for (int i = 0; i < LL; i++) {
        size_t idx = base + (size_t)i * ND;
        float kt = kArr[idx];
        float vt = vArr[idx];
        float rt = rArr[idx];
        float ek  = __expf(kt);
        float ekv = ek * vt;
        float numer = fmaf(eu, ekv, num);
        float denom = fmaf(eu, ek, den) + 1e-9f;
        float yy = rt * (numer / denom);
        y[idx] = yy;
        s1 += yy;
        s2 = fmaf(yy, yy, s2);
        num = fmaf(num, w, ekv);
        den = fmaf(den, w, ek);
    }

#pragma unroll
    for (int off = 16; off > 0; off >>= 1) {
        s1 += __shfl_down_sync(0xffffffffu, s1, off);
        s2 += __shfl_down_sync(0xffffffffu, s2, off);
    }
    __shared__ float sh1[2], sh2[2];
    int wd = kk >> 5;
    if ((kk & 31) == 0) { sh1[wd] = s1; sh2[wd] = s2; }
    __syncthreads();
    if (kk == 0) {
        atomicAdd(&g_s1[bh], sh1[0] + sh1[1]);
        atomicAdd(&g_s2[bh], sh2[0] + sh2[1]);
    }
}

// ---------------------------------------------------------------------------
// 4) GroupNorm apply fused with bf16 hi/lo split (y -> g_xrh/g_xrl)
// ---------------------------------------------------------------------------
__global__ void norm_bf16(const float* __restrict__ gnw,
                          const float* __restrict__ gnb)
{
    size_t idx = (size_t)blockIdx.x * blockDim.x + threadIdx.x;
    const size_t n8 = (size_t)NM * ND / 8;
    if (idx >= n8) return;
    size_t e = idx * 8;
    int d = (int)(e % ND);
    int b = (int)(e / ((size_t)NT * ND));
    int h = d >> 6;
    int bh = b * NH + h;

    const float inv = 1.f / (float)(NT * NK);
    float mean = g_s1[bh] * inv;
    float var  = g_s2[bh] * inv - mean * mean;
    float rstd = rsqrtf(var + 1e-5f);

    float4 y0 = ((const float4*)g_buf2)[idx*2];
    float4 y1 = ((const float4*)g_buf2)[idx*2 + 1];
    float4 w0 = ((const float4*)gnw)[d>>2], w1 = ((const float4*)gnw)[(d>>2)+1];
    float4 b0 = ((const float4*)gnb)[d>>2], b1 = ((const float4*)gnb)[(d>>2)+1];

    float yv[8] = {y0.x,y0.y,y0.z,y0.w,y1.x,y1.y,y1.z,y1.w};
    float wv[8] = {w0.x,w0.y,w0.z,w0.w,w1.x,w1.y,w1.z,w1.w};
    float bv[8] = {b0.x,b0.y,b0.z,b0.w,b1.x,b1.y,b1.z,b1.w};
    float m[8];
#pragma unroll
    for (int i = 0; i < 8; i++)
        m[i] = (yv[i] - mean) * rstd * wv[i] + bv[i];

    uint4 hi, lo;
    split8(m, hi, lo);
    ((uint4*)g_xrh)[idx] = hi;
    ((uint4*)g_xrl)[idx] = lo;
}

// ---------------------------------------------------------------------------
// host launcher
// ---------------------------------------------------------------------------
extern "C" void kernel_launch(void* const* d_in, const int* in_sizes, int n_in,
                              void* d_out, int out_size)
{
    const float* x   = (const float*)d_in[0];
    const float* tmr = (const float*)d_in[1];
    const float* tmk = (const float*)d_in[2];
    const float* tmv = (const float*)d_in[3];
    const float* td  = (const float*)d_in[4];
    const float* tf  = (const float*)d_in[5];
    const float* Wr  = (const float*)d_in[6];
    const float* Wk  = (const float*)d_in[7];
    const float* Wv  = (const float*)d_in[8];
    const float* Wo  = (const float*)d_in[9];
    const float* gnw = (const float*)d_in[10];
    const float* gnb = (const float*)d_in[11];
    float* out = (float*)d_out;

    float *b0, *b1, *b2, *b3;
    cudaGetSymbolAddress((void**)&b0, g_buf0);
    cudaGetSymbolAddress((void**)&b1, g_buf1);
    cudaGetSymbolAddress((void**)&b2, g_buf2);
    cudaGetSymbolAddress((void**)&b3, g_buf3);
    __nv_bfloat16 *xrh, *xrl, *xkh, *xkl, *xvh, *xvl, *wh, *wl;
    cudaGetSymbolAddress((void**)&xrh, g_xrh);
    cudaGetSymbolAddress((void**)&xrl, g_xrl);
    cudaGetSymbolAddress((void**)&xkh, g_xkh);
    cudaGetSymbolAddress((void**)&xkl, g_xkl);
    cudaGetSymbolAddress((void**)&xvh, g_xvh);
    cudaGetSymbolAddress((void**)&xvl, g_xvl);
    cudaGetSymbolAddress((void**)&wh, g_Wh);
    cudaGetSymbolAddress((void**)&wl, g_Wl);

    cudaFuncSetAttribute((const void*)gemm_mma_batched,
                         cudaFuncAttributeMaxDynamicSharedMemorySize, GEMM_SMEM_BYTES);

    const size_t n8 = (size_t)NM * ND / 8;
    const int blk = 256;
    const int grd8 = (int)((n8 + blk - 1) / blk);
    const int wn8 = ND * ND / 8;
    const int wgrd = (wn8 + blk - 1) / blk;

    // weight splits
    split_kernel<<<wgrd, blk>>>(Wr, wh + 0*(size_t)ND*ND, wl + 0*(size_t)ND*ND, wn8);
    split_kernel<<<wgrd, blk>>>(Wk, wh + 1*(size_t)ND*ND, wl + 1*(size_t)ND*ND, wn8);
    split_kernel<<<wgrd, blk>>>(Wv, wh + 2*(size_t)ND*ND, wl + 2*(size_t)ND*ND, wn8);
    split_kernel<<<wgrd, blk>>>(Wo, wh + 3*(size_t)ND*ND, wl + 3*(size_t)ND*ND, wn8);

    // token-shift mix + bf16 split
    mix_bf16<<<grd8, blk>>>(x, tmr, tmk, tmv);

    // fused r/k/v projections (batched over z)
    GemmArgs qkv;
    qkv.Ah[0] = xrh; qkv.Al[0] = xrl;
    qkv.Bh[0] = wh + 0*(size_t)ND*ND; qkv.Bl[0] = wl + 0*(size_t)ND*ND;
    qkv.C[0]  = b3;                 // r (sigmoid)
    qkv.Ah[1] = xkh; qkv.Al[1] = xkl;
    qkv.Bh[1] = wh + 1*(size_t)ND*ND; qkv.Bl[1] = wl + 1*(size_t)ND*ND;
    qkv.C[1]  = b0;                 // k
    qkv.Ah[2] = xvh; qkv.Al[2] = xvl;
    qkv.Bh[2] = wh + 2*(size_t)ND*ND; qkv.Bl[2] = wl + 2*(size_t)ND*ND;
    qkv.C[2]  = b1;                 // v
    qkv.actmask = 1;
    dim3 ggrid(ND / BN, NM / BM, 3);
    gemm_mma_batched<<<ggrid, 256, GEMM_SMEM_BYTES>>>(qkv);

    // chunked parallel WKV scan: y -> b2
    dim3 wgrid(NB * NH, CC);
    wkv_chunk_agg <<<wgrid, 64>>>(b0, b1, td);
    wkv_chunk_scan<<<NB * NH, 64>>>(td);
    wkv_out       <<<wgrid, 64>>>(b0, b1, b3, td, tf, b2);

    // GroupNorm apply + split (y -> xrh/xrl)
    norm_bf16<<<grd8, blk>>>(gnw, gnb);

    // output projection
    GemmArgs og;
    og.Ah[0] = xrh; og.Al[0] = xrl;
    og.Bh[0] = wh + 3*(size_t)ND*ND; og.Bl[0] = wl + 3*(size_t)ND*ND;
    og.C[0]  = out;
    og.Ah[1] = og.Ah[2] = xrh; og.Al[1] = og.Al[2] = xrl;
    og.Bh[1] = og.Bh[2] = og.Bh[0]; og.Bl[1] = og.Bl[2] = og.Bl[0];
    og.C[1] = og.C[2] = out;
    og.actmask = 0;
    dim3 ogrid(ND / BN, NM / BM, 1);
    gemm_mma_batched<<<ogrid, 256, GEMM_SMEM_BYTES>>>(og);
}